// round 10
// baseline (speedup 1.0000x reference)
#include <cuda_runtime.h>
#include <math.h>

// ---------------------------------------------------------------------------
// BondUpdateLayer, round 9: 512-thread CTAs (16 warps, 4/SMSP) for latency
// hiding. Warp = 8 output cols (one head), lane = 4 rows @ stride 32.
// Unmerged GEMMs, single 2-buffer cp.async weight ring, Xs kept live.
// Fix vs round 8: SMEM_T allocates the full 256 floats for kjS/jiS.
// ---------------------------------------------------------------------------

#define EN    80000
#define TMAXN 640000
#define NT    512

typedef unsigned long long ull;

__device__ float g_rfeat [EN * 20];
__device__ float g_q     [EN * 128];
__device__ float g_logits[(size_t)TMAXN * 16];
__device__ float g_v     [(size_t)TMAXN * 128];

__device__ __forceinline__ ull pack2(float v) {
    ull r;
    asm("mov.b64 %0, {%1, %1};" : "=l"(r) : "f"(v));
    return r;
}
__device__ __forceinline__ void fma2(ull& d, ull a, ull b) {
    asm("fma.rn.f32x2 %0, %1, %2, %0;" : "+l"(d) : "l"(a), "l"(b));
}
__device__ __forceinline__ float2 unpack2(ull v) {
    float lo, hi;
    asm("mov.b64 {%0, %1}, %2;" : "=f"(lo), "=f"(hi) : "l"(v));
    return make_float2(lo, hi);
}

#define CP_COMMIT() asm volatile("cp.async.commit_group;")
#define CP_WAIT1()  asm volatile("cp.async.wait_group 1;")

// ---- cp.async weight chunk loader (no commit): 32 k-rows x 128 cols ----
__device__ __forceinline__ void load_chunk_nc(const float* __restrict__ W, int kdim,
                                              int c, float* dst, int tid)
{
    #pragma unroll
    for (int i = 0; i < 2; i++) {
        int v = tid + i * NT;             // 0..1023 float4 slots
        int krow = c * 32 + (v >> 5);
        float* d = dst + v * 4;
        if (krow < kdim) {
            unsigned sa = (unsigned)__cvta_generic_to_shared(d);
            const float* s = W + (size_t)krow * 128 + (v & 31) * 4;
            asm volatile("cp.async.cg.shared.global [%0], [%1], 16;" :: "r"(sa), "l"(s));
        } else {
            d[0] = 0.f; d[1] = 0.f; d[2] = 0.f; d[3] = 0.f;
        }
    }
}

// ---- one 32-k GEMM chunk: warp owns 8 cols, lane owns 4 rows @ stride 32 ----
__device__ __forceinline__ void gemm_chunk(const float* __restrict__ Xl, int xstride,
                                           const float* __restrict__ Wp, int w8,
                                           ull acc[4][4])
{
    #pragma unroll
    for (int kq = 0; kq < 8; ++kq) {
        float4 act[4];
        #pragma unroll
        for (int rr = 0; rr < 4; rr++)
            act[rr] = *(const float4*)(Xl + rr * 32 * xstride + kq * 4);
        #pragma unroll
        for (int k4 = 0; k4 < 4; ++k4) {
            const ulonglong2* wp = (const ulonglong2*)(Wp + (kq * 4 + k4) * 128 + w8);
            ulonglong2 wA = wp[0], wB = wp[1];
            #pragma unroll
            for (int rr = 0; rr < 4; rr++) {
                float a = (k4 == 0) ? act[rr].x : (k4 == 1) ? act[rr].y
                        : (k4 == 2) ? act[rr].z : act[rr].w;
                ull ap = pack2(a);
                fma2(acc[rr][0], ap, wA.x);
                fma2(acc[rr][1], ap, wA.y);
                fma2(acc[rr][2], ap, wB.x);
                fma2(acc[rr][3], ap, wB.y);
            }
        }
    }
}

// ---- bias + LayerNorm + ReLU: acc -> Hs (stride 132). 2 internal syncs. ----
__device__ __forceinline__ void ln_relu(ull acc[4][4],
    const float* __restrict__ b1, const float* __restrict__ gam,
    const float* __restrict__ bet,
    float* Hs, float* red, float* mus, float* rss,
    int tid, int l, int w)
{
    const int w8 = w * 8;
    float a1[4][8];
    #pragma unroll
    for (int r = 0; r < 4; r++) {
        float s = 0.f, s2 = 0.f;
        #pragma unroll
        for (int cp = 0; cp < 4; cp++) {
            float2 t = unpack2(acc[r][cp]);
            float x0 = t.x + b1[w8 + cp * 2];
            float x1 = t.y + b1[w8 + cp * 2 + 1];
            a1[r][cp * 2]     = x0;
            a1[r][cp * 2 + 1] = x1;
            s += x0 + x1; s2 += x0 * x0 + x1 * x1;
        }
        int row = r * 32 + l;
        red[row * 17 + w]        = s;
        red[2176 + row * 17 + w] = s2;
    }
    __syncthreads();
    if (tid < 128) {
        float s = 0.f, s2 = 0.f;
        #pragma unroll
        for (int i = 0; i < 16; i++) { s += red[tid * 17 + i]; s2 += red[2176 + tid * 17 + i]; }
        float mu  = s * (1.f / 128.f);
        float var = fmaxf(s2 * (1.f / 128.f) - mu * mu, 0.f);
        mus[tid] = mu;
        rss[tid] = rsqrtf(var + 1e-5f);
    }
    __syncthreads();
    #pragma unroll
    for (int r = 0; r < 4; r++) {
        int row = r * 32 + l;
        float mu = mus[row], rs = rss[row];
        float4 hv[2];
        #pragma unroll
        for (int c = 0; c < 8; c++) {
            float h = gam[w8 + c] * (a1[r][c] - mu) * rs + bet[w8 + c];
            ((float*)hv)[c] = fmaxf(h, 0.f);
        }
        float4* hp = (float4*)(Hs + row * 132 + w8);
        hp[0] = hv[0]; hp[1] = hv[1];
    }
}

// ---- full MLP (512-thread layout). Requires W1 chunks 0,1 already committed.
__device__ __forceinline__ void mlp512(
    const float* __restrict__ Xs, int xstride, int n1, int kdim1,
    const float* __restrict__ b1,
    const float* __restrict__ gam, const float* __restrict__ bet,
    const float* __restrict__ W1,
    const float* __restrict__ W2, const float* __restrict__ b2,
    float* Hs, float* Wb, float* red, float* mus, float* rss,
    int tid, int l, int w, float out[4][8])
{
    const int w8 = w * 8;
    ull a1p[4][4];
    #pragma unroll
    for (int r = 0; r < 4; r++)
        #pragma unroll
        for (int c = 0; c < 4; c++) a1p[r][c] = 0ULL;

    const float* Xl = Xs + l * xstride;

    for (int c = 0; c < n1; c++) {
        CP_WAIT1();
        __syncthreads();
        gemm_chunk(Xl + c * 32, xstride, Wb + (c & 1) * 4096, w8, a1p);
        __syncthreads();
        if (c + 2 < n1) load_chunk_nc(W1, kdim1, c + 2, Wb + (c & 1) * 4096, tid);
        CP_COMMIT();
    }
    load_chunk_nc(W2, 128, 0, Wb + 0,    tid); CP_COMMIT();
    load_chunk_nc(W2, 128, 1, Wb + 4096, tid); CP_COMMIT();

    ln_relu(a1p, b1, gam, bet, Hs, red, mus, rss, tid, l, w);

    ull a2p[4][4];
    #pragma unroll
    for (int r = 0; r < 4; r++)
        #pragma unroll
        for (int c = 0; c < 4; c++) a2p[r][c] = 0ULL;

    const float* Hl = Hs + l * 132;
    for (int c = 0; c < 4; c++) {
        CP_WAIT1();
        __syncthreads();
        gemm_chunk(Hl + c * 32, 132, Wb + (c & 1) * 4096, w8, a2p);
        __syncthreads();
        if (c + 2 < 4) load_chunk_nc(W2, 128, c + 2, Wb + (c & 1) * 4096, tid);
        CP_COMMIT();
    }
    #pragma unroll
    for (int r = 0; r < 4; r++)
        #pragma unroll
        for (int cp = 0; cp < 4; cp++) {
            float2 t = unpack2(a2p[r][cp]);
            out[r][cp * 2]     = t.x + b2[w8 + cp * 2];
            out[r][cp * 2 + 1] = t.y + b2[w8 + cp * 2 + 1];
        }
}

// ---------------- K1a: edge gaussian features ----------------
__global__ void edge_feat_kernel(const float* __restrict__ pos,
                                 const int* __restrict__ brow,
                                 const int* __restrict__ bcol, int E)
{
    int e = blockIdx.x * blockDim.x + threadIdx.x;
    if (e >= E) return;
    int r = brow[e], c = bcol[e];
    float dx = pos[c*3+0] - pos[r*3+0];
    float dy = pos[c*3+1] - pos[r*3+1];
    float dz = pos[c*3+2] - pos[r*3+2];
    float d  = sqrtf(dx*dx + dy*dy + dz*dz);
    const float step  = 10.0f / 19.0f;
    const float coeff = -0.5f / (step * step);
    #pragma unroll
    for (int g = 0; g < 20; ++g) {
        float t = d - step * (float)g;
        g_rfeat[e*20 + g] = expf(coeff * t * t);
    }
}

// ---------------- K1b: Q MLP over edges ----------------
__global__ void __launch_bounds__(NT, 1) q_mlp_kernel(const float* __restrict__ h_bond,
    const float* __restrict__ W1, const float* __restrict__ b1,
    const float* __restrict__ gam, const float* __restrict__ bet,
    const float* __restrict__ W2, const float* __restrict__ b2, int E)
{
    extern __shared__ float sm[];
    float* Xs  = sm;                   // 128*132
    float* Hs  = Xs + 128*132;         // 128*132
    float* Wb  = Hs + 128*132;         // 2*4096
    float* red = Wb + 2*4096;          // 2*2176
    float* mus = red + 2*2176;         // 128
    float* rss = mus + 128;            // 128
    int tid = threadIdx.x, l = tid & 31, w = tid >> 5;
    int e0 = blockIdx.x * 128;

    load_chunk_nc(W1, 128, 0, Wb + 0,    tid); CP_COMMIT();
    load_chunk_nc(W1, 128, 1, Wb + 4096, tid); CP_COMMIT();

    for (int v = tid; v < 128*32; v += NT) {
        int row = v >> 5, c4 = v & 31;
        float4 x = make_float4(0.f, 0.f, 0.f, 0.f);
        if (e0 + row < E) x = ((const float4*)h_bond)[(size_t)(e0 + row)*32 + c4];
        float* xr = Xs + row*132 + c4*4;
        xr[0] = x.x; xr[1] = x.y; xr[2] = x.z; xr[3] = x.w;
    }

    float out[4][8];
    mlp512(Xs, 132, 4, 128, b1, gam, bet, W1, W2, b2,
           Hs, Wb, red, mus, rss, tid, l, w, out);

    #pragma unroll
    for (int r = 0; r < 4; r++) {
        int row = r * 32 + l;
        int e = e0 + row;
        if (e < E) {
            float4* qp = (float4*)(g_q + (size_t)e*128 + w*8);
            qp[0] = *(float4*)&out[r][0];
            qp[1] = *(float4*)&out[r][4];
        }
    }
}

// ---------------- K2: triplet kv -> hk (logits), hv (V) ----------------
__global__ void __launch_bounds__(NT, 1) triplet_kernel(
    const float* __restrict__ h_bond, const float* __restrict__ pos,
    const float* __restrict__ kW1, const float* __restrict__ kb1,
    const float* __restrict__ kg,  const float* __restrict__ kb,
    const float* __restrict__ kW2, const float* __restrict__ kb2,
    const float* __restrict__ vW1, const float* __restrict__ vb1,
    const float* __restrict__ vg,  const float* __restrict__ vb,
    const float* __restrict__ vW2, const float* __restrict__ vb2,
    const int* __restrict__ idx_i, const int* __restrict__ idx_j,
    const int* __restrict__ idx_k, const int* __restrict__ idx_kj,
    const int* __restrict__ idx_ji, int blk0, int T)
{
    extern __shared__ float sm[];
    const int XS = 196;                 // 192 data cols + 4 pad (== 4 mod 32)
    float* Xs  = sm;                    // 128*196 (stays live for both MLPs)
    float* Hs  = Xs + 128*XS;           // 128*132
    float* Wb  = Hs + 128*132;          // 2*4096
    float* red = Wb + 2*4096;           // 2*2176
    float* mus = red + 2*2176;          // 128
    float* rss = mus + 128;             // 128
    int*   kjS = (int*)(rss + 128);     // 128
    int*   jiS = kjS + 128;             // 128

    int tid = threadIdx.x, l = tid & 31, w = tid >> 5;
    const int w8 = w * 8;
    int t0 = (blockIdx.x + blk0) * 128;

    // prefetch hk W1 chunks 0,1 (overlaps assembly)
    load_chunk_nc(kW1, 181, 0, Wb + 0,    tid); CP_COMMIT();
    load_chunk_nc(kW1, 181, 1, Wb + 4096, tid); CP_COMMIT();

    // zero tail cols 176..195
    for (int v = tid; v < 128*5; v += NT) {
        int row = v / 5, c4 = v % 5;
        ((float4*)(Xs + row*XS + 176))[c4] = make_float4(0.f, 0.f, 0.f, 0.f);
    }
    __syncthreads();

    // per-row indices + angular features (cols 168..180)
    if (tid < 128) {
        int t = t0 + tid;
        if (t < T) {
            int kj = idx_kj[t], ji = idx_ji[t];
            kjS[tid] = kj; jiS[tid] = ji;
            int ii = idx_i[t], jj = idx_j[t], kk = idx_k[t];
            float pix = pos[ii*3+0], piy = pos[ii*3+1], piz = pos[ii*3+2];
            float jx = pos[jj*3+0]-pix, jy = pos[jj*3+1]-piy, jz = pos[jj*3+2]-piz;
            float kx = pos[kk*3+0]-pix, ky = pos[kk*3+1]-piy, kz = pos[kk*3+2]-piz;
            float dt = jx*kx + jy*ky + jz*kz;
            float cx = jy*kz - jz*ky, cy = jz*kx - jx*kz, cz = jx*ky - jy*kx;
            float cr = sqrtf(cx*cx + cy*cy + cz*cz);
            float ang = atan2f(cr, dt);
            float* xr = Xs + tid*XS + 168;
            xr[0] = ang;
            const float fq[6] = {1.f, 2.f, 3.f, 1.f, 0.5f, 1.f/3.f};
            #pragma unroll
            for (int i = 0; i < 6; i++) {
                xr[1 + i] = sinf(ang * fq[i]);
                xr[7 + i] = cosf(ang * fq[i]);
            }
        } else {
            kjS[tid] = -1; jiS[tid] = -1;
            float* xr = Xs + tid*XS;
            #pragma unroll
            for (int c4 = 0; c4 < 44; c4++)
                ((float4*)xr)[c4] = make_float4(0.f, 0.f, 0.f, 0.f);
        }
    }
    __syncthreads();

    // h_bond[idx_kj] gather -> cols 0..127
    for (int v = tid; v < 128*32; v += NT) {
        int row = v >> 5, c4 = v & 31;
        int kj = kjS[row];
        if (kj >= 0) {
            float4 hb = ((const float4*)h_bond)[(size_t)kj*32 + c4];
            float* xr = Xs + row*XS + c4*4;
            xr[0] = hb.x; xr[1] = hb.y; xr[2] = hb.z; xr[3] = hb.w;
        }
    }
    // rfeat gathers -> cols 128..147 (kj), 148..167 (ji)
    for (int v = tid; v < 128*20; v += NT) {
        int row = v / 20, g = v % 20;
        int kj = kjS[row];
        if (kj >= 0) {
            Xs[row*XS + 128 + g] = g_rfeat[kj*20 + g];
            Xs[row*XS + 148 + g] = g_rfeat[jiS[row]*20 + g];
        }
    }

    // -------- hk MLP --------
    float out[4][8];
    mlp512(Xs, XS, 6, 181, kb1, kg, kb, kW1, kW2, kb2,
           Hs, Wb, red, mus, rss, tid, l, w, out);

    // prefetch hv W1 (overlaps logits epilogue)
    load_chunk_nc(vW1, 181, 0, Wb + 0,    tid); CP_COMMIT();
    load_chunk_nc(vW1, 181, 1, Wb + 4096, tid); CP_COMMIT();

    // -------- logits epilogue (warp w == head w) --------
    const float scale = 0.3535533905932738f;  // 1/sqrt(8)
    #pragma unroll
    for (int r = 0; r < 4; r++) {
        int row = r * 32 + l;
        int ji = jiS[row];
        if (ji >= 0) {
            const float4* qp = (const float4*)(g_q + (size_t)ji*128 + w8);
            float4 q0 = qp[0], q1 = qp[1];
            float lg = out[r][0]*q0.x + out[r][1]*q0.y + out[r][2]*q0.z + out[r][3]*q0.w
                     + out[r][4]*q1.x + out[r][5]*q1.y + out[r][6]*q1.z + out[r][7]*q1.w;
            g_logits[(size_t)(t0 + row)*16 + w] = lg * scale;
        }
    }

    // -------- hv MLP (Xs still live) --------
    mlp512(Xs, XS, 6, 181, vb1, vg, vb, vW1, vW2, vb2,
           Hs, Wb, red, mus, rss, tid, l, w, out);

    #pragma unroll
    for (int r = 0; r < 4; r++) {
        int row = r * 32 + l;
        if (jiS[row] >= 0) {
            float4* vp = (float4*)(g_v + (size_t)(t0 + row)*128 + w8);
            vp[0] = *(float4*)&out[r][0];
            vp[1] = *(float4*)&out[r][4];
        }
    }
}

// ---------------- K3: per-edge segment softmax + weighted V sum ----------------
__global__ void attn_out_kernel(const int* __restrict__ idx_ji,
                                int T, int E, float* __restrict__ out)
{
    int warp = (blockIdx.x * blockDim.x + threadIdx.x) >> 5;
    int lane = threadIdx.x & 31;
    if (warp >= E) return;
    int e = warp;

    int lo = 0, hi = T;
    while (lo < hi) { int m = (lo + hi) >> 1; if (idx_ji[m] <  e)     lo = m + 1; else hi = m; }
    int s = lo;
    int hi2 = T;
    while (lo < hi2) { int m = (lo + hi2) >> 1; if (idx_ji[m] < e + 1) lo = m + 1; else hi2 = m; }
    int en = lo;

    int head = lane >> 1, half = lane & 1;

    float mx = -INFINITY;
    for (int t = s; t < en; t++) mx = fmaxf(mx, g_logits[(size_t)t*16 + head]);

    float den = 0.f;
    float ax = 0.f, ay = 0.f, az = 0.f, aw = 0.f;
    for (int t = s; t < en; t++) {
        float w = expf(g_logits[(size_t)t*16 + head] - mx);
        den += w;
        float4 v = *(const float4*)(g_v + (size_t)t*128 + head*8 + half*4);
        ax += w * v.x; ay += w * v.y; az += w * v.z; aw += w * v.w;
    }
    float inv = (en > s) ? (1.f / den) : 0.f;
    float4 o = make_float4(ax * inv, ay * inv, az * inv, aw * inv);
    *(float4*)(out + (size_t)e*128 + head*8 + half*4) = o;
}

// ---------------- launcher ----------------
extern "C" void kernel_launch(void* const* d_in, const int* in_sizes, int n_in,
                              void* d_out, int out_size)
{
    const float* h_bond = (const float*)d_in[1];
    const float* pos    = (const float*)d_in[2];
    const float* kW1 = (const float*)d_in[3];
    const float* kb1 = (const float*)d_in[4];
    const float* kg  = (const float*)d_in[5];
    const float* kb  = (const float*)d_in[6];
    const float* kW2 = (const float*)d_in[7];
    const float* kb2 = (const float*)d_in[8];
    const float* vW1 = (const float*)d_in[9];
    const float* vb1 = (const float*)d_in[10];
    const float* vg  = (const float*)d_in[11];
    const float* vb  = (const float*)d_in[12];
    const float* vW2 = (const float*)d_in[13];
    const float* vb2 = (const float*)d_in[14];
    const float* qW1 = (const float*)d_in[15];
    const float* qb1 = (const float*)d_in[16];
    const float* qg  = (const float*)d_in[17];
    const float* qb  = (const float*)d_in[18];
    const float* qW2 = (const float*)d_in[19];
    const float* qb2 = (const float*)d_in[20];
    const int* bond_row = (const int*)d_in[21];
    const int* bond_col = (const int*)d_in[22];
    const int* idx_i  = (const int*)d_in[23];
    const int* idx_j  = (const int*)d_in[24];
    const int* idx_k  = (const int*)d_in[25];
    const int* idx_kj = (const int*)d_in[26];
    const int* idx_ji = (const int*)d_in[27];
    int E = in_sizes[21];
    int T = in_sizes[23];

    // triplet smem: Xs(128*196) + Hs(128*132) + Wb(2*4096) + red(2*2176)
    //             + mus/rss(256) + kjS/jiS(256)
    const int SMEM_T = (128*196 + 128*132 + 2*4096 + 2*2176 + 256 + 256) * 4; // 220,160 B
    const int SMEM_Q = (128*132 + 128*132 + 2*4096 + 2*2176 + 256) * 4;       // 186,368 B
    cudaFuncSetAttribute(q_mlp_kernel,   cudaFuncAttributeMaxDynamicSharedMemorySize, SMEM_Q);
    cudaFuncSetAttribute(triplet_kernel, cudaFuncAttributeMaxDynamicSharedMemorySize, SMEM_T);

    int nb  = (T + 127) / 128;
    int nbA = nb / 2; if (nbA < 1) nbA = 1;
    int nbB = nb - nbA;

    edge_feat_kernel<<<(E + 255) / 256, 256>>>(pos, bond_row, bond_col, E);
    q_mlp_kernel<<<(E + 127) / 128, NT, SMEM_Q>>>(h_bond, qW1, qb1, qg, qb, qW2, qb2, E);
    triplet_kernel<<<nbA, NT, SMEM_T>>>(
        h_bond, pos,
        kW1, kb1, kg, kb, kW2, kb2,
        vW1, vb1, vg, vb, vW2, vb2,
        idx_i, idx_j, idx_k, idx_kj, idx_ji, 0, T);
    if (nbB > 0)
        triplet_kernel<<<nbB, NT, SMEM_T>>>(
            h_bond, pos,
            kW1, kb1, kg, kb, kW2, kb2,
            vW1, vb1, vg, vb, vW2, vb2,
            idx_i, idx_j, idx_k, idx_kj, idx_ji, nbA, T);
    attn_out_kernel<<<(E * 32 + 255) / 256, 256>>>(idx_ji, T, E, (float*)d_out);
}

// round 12
// speedup vs baseline: 1.6814x; 1.6814x over previous
#include <cuda_runtime.h>
#include <cuda_fp16.h>
#include <math.h>
#include <stdint.h>

// ---------------------------------------------------------------------------
// BondUpdateLayer, round 12: mma.sync.m16n8k16 (f16 in, f32 acc; sm_80 PTX,
// legal at target sm_103) for the triplet MLPs with fp16-split fp32 emulation
// (3 passes: xh*wh + xh*wl + xl*wh). Weights pre-packed into per-lane fragment
// order by a prep kernel (no swizzle/ldmatrix/tcgen05). q_mlp/attn/edge = r9.
// ---------------------------------------------------------------------------

#define EN    80000
#define TMAXN 640000
#define NTQ   512

typedef unsigned long long ull;

__device__ float g_rfeat [EN * 20];
__device__ float g_q     [EN * 128];
__device__ float g_logits[(size_t)TMAXN * 16];
__device__ float g_v     [(size_t)TMAXN * 128];
// fragment-packed weight words (half2 per word):
// kW1h@0, kW1l@12288, vW1h@24576, vW1l@36864 (12288 words each: 12 k16)
// kW2h@49152, kW2l@57344, vW2h@65536, vW2l@73728 (8192 words each: 8 k16)
__device__ __align__(16) uint32_t g_Bw[81920];

// ---------------- helpers ----------------
__device__ __forceinline__ ull pack2(float v) {
    ull r; asm("mov.b64 %0, {%1, %1};" : "=l"(r) : "f"(v)); return r;
}
__device__ __forceinline__ void fma2(ull& d, ull a, ull b) {
    asm("fma.rn.f32x2 %0, %1, %2, %0;" : "+l"(d) : "l"(a), "l"(b));
}
__device__ __forceinline__ float2 unpack2(ull v) {
    float lo, hi; asm("mov.b64 {%0, %1}, %2;" : "=f"(lo), "=f"(hi) : "l"(v));
    return make_float2(lo, hi);
}
__device__ __forceinline__ void split2(float f0, float f1, uint32_t& hi, uint32_t& lo) {
    __half h0 = __float2half_rn(f0), h1 = __float2half_rn(f1);
    __half l0 = __float2half_rn(f0 - __half2float(h0));
    __half l1 = __float2half_rn(f1 - __half2float(h1));
    __half2 H = __halves2half2(h0, h1), L = __halves2half2(l0, l1);
    hi = *(uint32_t*)&H; lo = *(uint32_t*)&L;
}
__device__ __forceinline__ void mma16816(float c[4], uint32_t a0, uint32_t a1,
                                         uint32_t a2, uint32_t a3,
                                         uint32_t b0, uint32_t b1) {
    asm volatile(
        "mma.sync.aligned.m16n8k16.row.col.f32.f16.f16.f32 "
        "{%0,%1,%2,%3},{%4,%5,%6,%7},{%8,%9},{%0,%1,%2,%3};"
        : "+f"(c[0]), "+f"(c[1]), "+f"(c[2]), "+f"(c[3])
        : "r"(a0), "r"(a1), "r"(a2), "r"(a3), "r"(b0), "r"(b1));
}

// ---------------- weight prep: pack into fragment order ----------------
// word layout per image: idx = ((k16*16 + n8)*32 + lane)*2 + r
// b0(r=0): halves W[k16*16 + (lane&3)*2 + {0,1}][n8*8 + (lane>>2)]
// b1(r=1): same with k += 8
__global__ void prep_weights(const float* __restrict__ kW1, const float* __restrict__ vW1,
                             const float* __restrict__ kW2, const float* __restrict__ vW2)
{
    int word = blockIdx.x * 1024 + threadIdx.x;
    const float* W; int kdim, rem; bool lo;
    if (word < 49152) {
        int img = word / 12288; rem = word % 12288;
        W = (img < 2) ? kW1 : vW1; lo = img & 1; kdim = 181;
    } else {
        int w2 = word - 49152;
        int img = w2 / 8192; rem = w2 % 8192;
        W = (img < 2) ? kW2 : vW2; lo = img & 1; kdim = 128;
    }
    int r = rem & 1, lane = (rem >> 1) & 31, n8 = (rem >> 6) & 15, k16 = rem >> 10;
    int K = k16 * 16 + (lane & 3) * 2 + r * 8;
    int n = n8 * 8 + (lane >> 2);
    float w0 = (K     < kdim) ? W[(size_t)K * 128 + n]       : 0.f;
    float w1 = (K + 1 < kdim) ? W[(size_t)(K + 1) * 128 + n] : 0.f;
    __half h0 = __float2half_rn(w0), h1 = __float2half_rn(w1);
    if (lo) {
        h0 = __float2half_rn(w0 - __half2float(h0));
        h1 = __float2half_rn(w1 - __half2float(h1));
    }
    __half2 p = __halves2half2(h0, h1);
    g_Bw[word] = *(uint32_t*)&p;
}

// ---------------- weight chunk loader: 2 k16 (hi 2048 w + lo 2048 w) ----------
__device__ __forceinline__ void load_wc(const uint32_t* __restrict__ gHi,
                                        const uint32_t* __restrict__ gLo,
                                        int c, uint32_t* dst, int tid)
{
    #pragma unroll
    for (int i = 0; i < 4; i++) {
        int v = tid + i * 256;   // 0..1023 float4 slots
        const uint32_t* src = (v < 512) ? (gHi + c * 2048 + v * 4)
                                        : (gLo + c * 2048 + (v - 512) * 4);
        unsigned sa = (unsigned)__cvta_generic_to_shared(dst + v * 4);
        asm volatile("cp.async.cg.shared.global [%0], [%1], 16;" :: "r"(sa), "l"(src));
    }
}
#define CPC() asm volatile("cp.async.commit_group;")

// ---------------- one GEMM phase: acc += Ah@(Wh+Wl) + Al@Wh ----------------
__device__ __forceinline__ void gemm_phase(
    float acc[16][4], const __half* __restrict__ Ah, const __half* __restrict__ Al,
    int astride, int nk16,
    const uint32_t* __restrict__ gHi, const uint32_t* __restrict__ gLo,
    uint32_t* Wbuf, int R0, int t2, int lane, int tid)
{
    load_wc(gHi, gLo, 0, Wbuf, tid);        CPC();
    load_wc(gHi, gLo, 1, Wbuf + 4096, tid); CPC();
    int nch = nk16 >> 1;
    for (int c = 0; c < nch; c++) {
        asm volatile("cp.async.wait_group 1;");
        __syncthreads();
        const uint32_t* WB = Wbuf + (c & 1) * 4096;
        #pragma unroll
        for (int kl = 0; kl < 2; kl++) {
            int cb = (c * 2 + kl) * 16 + t2;
            const __half* xh = Ah + R0 * astride + cb;
            uint32_t a0 = *(const uint32_t*)(xh);
            uint32_t a1 = *(const uint32_t*)(xh + 8 * astride);
            uint32_t a2 = *(const uint32_t*)(xh + 8);
            uint32_t a3 = *(const uint32_t*)(xh + 8 * astride + 8);
            const uint32_t* bh = WB + kl * 1024 + lane * 2;
            #pragma unroll
            for (int n8 = 0; n8 < 16; n8++) {
                ull b = *(const ull*)(bh + n8 * 64);
                mma16816(acc[n8], a0, a1, a2, a3, (uint32_t)b, (uint32_t)(b >> 32));
            }
            const uint32_t* bl = bh + 2048;
            #pragma unroll
            for (int n8 = 0; n8 < 16; n8++) {
                ull b = *(const ull*)(bl + n8 * 64);
                mma16816(acc[n8], a0, a1, a2, a3, (uint32_t)b, (uint32_t)(b >> 32));
            }
            const __half* xl = Al + R0 * astride + cb;
            uint32_t l0 = *(const uint32_t*)(xl);
            uint32_t l1 = *(const uint32_t*)(xl + 8 * astride);
            uint32_t l2 = *(const uint32_t*)(xl + 8);
            uint32_t l3 = *(const uint32_t*)(xl + 8 * astride + 8);
            #pragma unroll
            for (int n8 = 0; n8 < 16; n8++) {
                ull b = *(const ull*)(bh + n8 * 64);
                mma16816(acc[n8], l0, l1, l2, l3, (uint32_t)b, (uint32_t)(b >> 32));
            }
        }
        __syncthreads();
        if (c + 2 < nch) load_wc(gHi, gLo, c + 2, Wbuf + (c & 1) * 4096, tid);
        CPC();
    }
}

// ---------------- LN + ReLU + split-store (warp-local) ----------------
__device__ __forceinline__ void ln_store(float acc[16][4],
    const float* __restrict__ gam, const float* __restrict__ bet,
    __half* HH, __half* HL, int R0, int t2)
{
    float s0 = 0.f, q0 = 0.f, s1 = 0.f, q1 = 0.f;
    #pragma unroll
    for (int n8 = 0; n8 < 16; n8++) {
        s0 += acc[n8][0] + acc[n8][1];
        q0 += acc[n8][0]*acc[n8][0] + acc[n8][1]*acc[n8][1];
        s1 += acc[n8][2] + acc[n8][3];
        q1 += acc[n8][2]*acc[n8][2] + acc[n8][3]*acc[n8][3];
    }
    #pragma unroll
    for (int o = 1; o < 4; o <<= 1) {
        s0 += __shfl_xor_sync(0xffffffffu, s0, o);
        q0 += __shfl_xor_sync(0xffffffffu, q0, o);
        s1 += __shfl_xor_sync(0xffffffffu, s1, o);
        q1 += __shfl_xor_sync(0xffffffffu, q1, o);
    }
    float mu0 = s0 * (1.f/128.f), mu1 = s1 * (1.f/128.f);
    float rs0 = rsqrtf(fmaxf(q0 * (1.f/128.f) - mu0*mu0, 0.f) + 1e-5f);
    float rs1 = rsqrtf(fmaxf(q1 * (1.f/128.f) - mu1*mu1, 0.f) + 1e-5f);
    int R1 = R0 + 8;
    #pragma unroll
    for (int n8 = 0; n8 < 16; n8++) {
        int col = 8 * n8 + t2;
        float g0 = gam[col], g1 = gam[col+1], b0 = bet[col], b1 = bet[col+1];
        float h00 = fmaxf(g0 * (acc[n8][0] - mu0) * rs0 + b0, 0.f);
        float h01 = fmaxf(g1 * (acc[n8][1] - mu0) * rs0 + b1, 0.f);
        float h10 = fmaxf(g0 * (acc[n8][2] - mu1) * rs1 + b0, 0.f);
        float h11 = fmaxf(g1 * (acc[n8][3] - mu1) * rs1 + b1, 0.f);
        uint32_t hi, lo;
        split2(h00, h01, hi, lo);
        *(uint32_t*)(HH + R0 * 136 + col) = hi;
        *(uint32_t*)(HL + R0 * 136 + col) = lo;
        split2(h10, h11, hi, lo);
        *(uint32_t*)(HH + R1 * 136 + col) = hi;
        *(uint32_t*)(HL + R1 * 136 + col) = lo;
    }
}

// ---------------- triplet kernel ----------------
// smem (bytes): XH 0(51200) XL 51200(51200) HH 102400(34816) HL 137216(34816)
// Wbuf 172032(32768) bias 204800(4096) kjS 208896(512) jiS 209408(512) = 209920
#define SMEM_T 209920

__global__ void __launch_bounds__(256, 1) triplet_mma_kernel(
    const float* __restrict__ h_bond, const float* __restrict__ pos,
    const float* __restrict__ kb1, const float* __restrict__ kg,
    const float* __restrict__ kb,  const float* __restrict__ kb2,
    const float* __restrict__ vb1, const float* __restrict__ vg,
    const float* __restrict__ vb,  const float* __restrict__ vb2,
    const int* __restrict__ idx_i, const int* __restrict__ idx_j,
    const int* __restrict__ idx_k, const int* __restrict__ idx_kj,
    const int* __restrict__ idx_ji, int blk0, int T)
{
    extern __shared__ char smem[];
    __half* XH = (__half*)(smem);
    __half* XL = (__half*)(smem + 51200);
    __half* HH = (__half*)(smem + 102400);
    __half* HL = (__half*)(smem + 137216);
    uint32_t* Wbuf = (uint32_t*)(smem + 172032);
    float* bias = (float*)(smem + 204800);
    int* kjS = (int*)(smem + 208896);
    int* jiS = (int*)(smem + 209408);

    int tid = threadIdx.x, lane = tid & 31, w = tid >> 5;
    int g = lane >> 2, t2 = (lane & 3) * 2;
    int R0 = w * 16 + g, R1 = R0 + 8;
    int t0 = (blockIdx.x + blk0) * 128;

    // zero XH+XL (102400 B = 6400 uint4)
    for (int v = tid; v < 6400; v += 256)
        ((uint4*)smem)[v] = make_uint4(0, 0, 0, 0);
    {
        const float* srcs[8] = {kb1, kg, kb, kb2, vb1, vg, vb, vb2};
        for (int v = tid; v < 1024; v += 256) bias[v] = srcs[v >> 7][v & 127];
    }
    __syncthreads();

    // indices + angular features (cols 168..181, col 181 written 0)
    if (tid < 128) {
        int t = t0 + tid;
        int kj = -1, ji = -1;
        float vals[14];
        #pragma unroll
        for (int p = 0; p < 14; p++) vals[p] = 0.f;
        if (t < T) {
            kj = idx_kj[t]; ji = idx_ji[t];
            int ii = idx_i[t], jj = idx_j[t], kk = idx_k[t];
            float pix = pos[ii*3+0], piy = pos[ii*3+1], piz = pos[ii*3+2];
            float jx = pos[jj*3+0]-pix, jy = pos[jj*3+1]-piy, jz = pos[jj*3+2]-piz;
            float kx = pos[kk*3+0]-pix, ky = pos[kk*3+1]-piy, kz = pos[kk*3+2]-piz;
            float dt = jx*kx + jy*ky + jz*kz;
            float cx = jy*kz - jz*ky, cy = jz*kx - jx*kz, cz = jx*ky - jy*kx;
            float cr = sqrtf(cx*cx + cy*cy + cz*cz);
            float ang = atan2f(cr, dt);
            vals[0] = ang;
            const float fq[6] = {1.f, 2.f, 3.f, 1.f, 0.5f, 1.f/3.f};
            #pragma unroll
            for (int i = 0; i < 6; i++) {
                vals[1 + i] = sinf(ang * fq[i]);
                vals[7 + i] = cosf(ang * fq[i]);
            }
        }
        kjS[tid] = kj; jiS[tid] = ji;
        #pragma unroll
        for (int p = 0; p < 7; p++) {
            uint32_t hi, lo;
            split2(vals[2*p], vals[2*p+1], hi, lo);
            *(uint32_t*)(XH + tid * 200 + 168 + 2*p) = hi;
            *(uint32_t*)(XL + tid * 200 + 168 + 2*p) = lo;
        }
    }
    __syncthreads();

    // h_bond[idx_kj] -> cols 0..127
    for (int v = tid; v < 128 * 32; v += 256) {
        int row = v >> 5, c4 = v & 31;
        int kj = kjS[row];
        if (kj >= 0) {
            float4 x = ((const float4*)h_bond)[(size_t)kj * 32 + c4];
            uint32_t h0, l0, h1, l1;
            split2(x.x, x.y, h0, l0); split2(x.z, x.w, h1, l1);
            *(uint2*)(XH + row * 200 + c4 * 4) = make_uint2(h0, h1);
            *(uint2*)(XL + row * 200 + c4 * 4) = make_uint2(l0, l1);
        }
    }
    // rfeat -> cols 128..147 (kj), 148..167 (ji)
    for (int v = tid; v < 128 * 20; v += 256) {
        int row = v / 20, u = v % 20;
        float f0 = 0.f, f1 = 0.f; int col; bool ok = false;
        if (u < 10) {
            int kj = kjS[row]; col = 128 + 2 * u;
            if (kj >= 0) { f0 = g_rfeat[kj*20 + 2*u]; f1 = g_rfeat[kj*20 + 2*u + 1]; ok = true; }
        } else {
            int j = u - 10, ji = jiS[row]; col = 148 + 2 * j;
            if (ji >= 0) { f0 = g_rfeat[ji*20 + 2*j]; f1 = g_rfeat[ji*20 + 2*j + 1]; ok = true; }
        }
        if (ok) {
            uint32_t hi, lo;
            split2(f0, f1, hi, lo);
            *(uint32_t*)(XH + row * 200 + col) = hi;
            *(uint32_t*)(XL + row * 200 + col) = lo;
        }
    }
    __syncthreads();

    float acc[16][4];

    // ======== k-MLP ========
    #pragma unroll
    for (int n8 = 0; n8 < 16; n8++) {
        float b0 = bias[3*128 + 0*384 + 0]; // placeholder avoided; use kb1 region:
        (void)b0;
        acc[n8][0] = bias[0*128 + 8*n8 + t2];
        acc[n8][1] = bias[0*128 + 8*n8 + t2 + 1];
        acc[n8][2] = acc[n8][0];
        acc[n8][3] = acc[n8][1];
    }
    gemm_phase(acc, XH, XL, 200, 12, g_Bw + 0, g_Bw + 12288, Wbuf, R0, t2, lane, tid);
    ln_store(acc, bias + 128, bias + 256, HH, HL, R0, t2);
    __syncthreads();

    #pragma unroll
    for (int n8 = 0; n8 < 16; n8++) {
        acc[n8][0] = bias[3*128 + 8*n8 + t2];
        acc[n8][1] = bias[3*128 + 8*n8 + t2 + 1];
        acc[n8][2] = acc[n8][0];
        acc[n8][3] = acc[n8][1];
    }
    gemm_phase(acc, HH, HL, 136, 8, g_Bw + 49152, g_Bw + 57344, Wbuf, R0, t2, lane, tid);

    // logits epilogue
    {
        int ji0 = jiS[R0], ji1 = jiS[R1];
        float lg0[16], lg1[16];
        #pragma unroll
        for (int n8 = 0; n8 < 16; n8++) { lg0[n8] = 0.f; lg1[n8] = 0.f; }
        if (ji0 >= 0) {
            #pragma unroll
            for (int n8 = 0; n8 < 16; n8++) {
                float2 qv = *(const float2*)(g_q + (size_t)ji0 * 128 + 8 * n8 + t2);
                lg0[n8] = acc[n8][0] * qv.x + acc[n8][1] * qv.y;
            }
        }
        if (ji1 >= 0) {
            #pragma unroll
            for (int n8 = 0; n8 < 16; n8++) {
                float2 qv = *(const float2*)(g_q + (size_t)ji1 * 128 + 8 * n8 + t2);
                lg1[n8] = acc[n8][2] * qv.x + acc[n8][3] * qv.y;
            }
        }
        #pragma unroll
        for (int o = 1; o < 4; o <<= 1)
            #pragma unroll
            for (int n8 = 0; n8 < 16; n8++) {
                lg0[n8] += __shfl_xor_sync(0xffffffffu, lg0[n8], o);
                lg1[n8] += __shfl_xor_sync(0xffffffffu, lg1[n8], o);
            }
        const float sc = 0.3535533905932738f;
        int tq = lane & 3;
        if (ji0 >= 0)
            *(float4*)(g_logits + (size_t)(t0 + R0) * 16 + 4 * tq) =
                make_float4(lg0[4*tq]*sc, lg0[4*tq+1]*sc, lg0[4*tq+2]*sc, lg0[4*tq+3]*sc);
        if (ji1 >= 0)
            *(float4*)(g_logits + (size_t)(t0 + R1) * 16 + 4 * tq) =
                make_float4(lg1[4*tq]*sc, lg1[4*tq+1]*sc, lg1[4*tq+2]*sc, lg1[4*tq+3]*sc);
    }

    // ======== v-MLP ========
    #pragma unroll
    for (int n8 = 0; n8 < 16; n8++) {
        acc[n8][0] = bias[4*128 + 8*n8 + t2];
        acc[n8][1] = bias[4*128 + 8*n8 + t2 + 1];
        acc[n8][2] = acc[n8][0];
        acc[n8][3] = acc[n8][1];
    }
    gemm_phase(acc, XH, XL, 200, 12, g_Bw + 24576, g_Bw + 36864, Wbuf, R0, t2, lane, tid);
    __syncthreads();           // GEMM2-k readers of HH done (phase-end sync) — extra safety
    ln_store(acc, bias + 5*128, bias + 6*128, HH, HL, R0, t2);
    __syncthreads();

    #pragma unroll
    for (int n8 = 0; n8 < 16; n8++) {
        acc[n8][0] = bias[7*128 + 8*n8 + t2];
        acc[n8][1] = bias[7*128 + 8*n8 + t2 + 1];
        acc[n8][2] = acc[n8][0];
        acc[n8][3] = acc[n8][1];
    }
    gemm_phase(acc, HH, HL, 136, 8, g_Bw + 65536, g_Bw + 73728, Wbuf, R0, t2, lane, tid);

    // V epilogue
    {
        int ji0 = jiS[R0], ji1 = jiS[R1];
        #pragma unroll
        for (int n8 = 0; n8 < 16; n8++) {
            int col = 8 * n8 + t2;
            if (ji0 >= 0)
                *(float2*)(g_v + (size_t)(t0 + R0) * 128 + col) =
                    make_float2(acc[n8][0], acc[n8][1]);
            if (ji1 >= 0)
                *(float2*)(g_v + (size_t)(t0 + R1) * 128 + col) =
                    make_float2(acc[n8][2], acc[n8][3]);
        }
    }
}

// ======================= r9 SIMT kernels (q/edge/attn) ==================
__device__ __forceinline__ void load_chunk_nc(const float* __restrict__ W, int kdim,
                                              int c, float* dst, int tid)
{
    #pragma unroll
    for (int i = 0; i < 2; i++) {
        int v = tid + i * NTQ;
        int krow = c * 32 + (v >> 5);
        float* d = dst + v * 4;
        if (krow < kdim) {
            unsigned sa = (unsigned)__cvta_generic_to_shared(d);
            const float* s = W + (size_t)krow * 128 + (v & 31) * 4;
            asm volatile("cp.async.cg.shared.global [%0], [%1], 16;" :: "r"(sa), "l"(s));
        } else { d[0]=0.f; d[1]=0.f; d[2]=0.f; d[3]=0.f; }
    }
}

__device__ __forceinline__ void gemm_chunk(const float* __restrict__ Xl, int xstride,
                                           const float* __restrict__ Wp, int w8, ull acc[4][4])
{
    #pragma unroll
    for (int kq = 0; kq < 8; ++kq) {
        float4 act[4];
        #pragma unroll
        for (int rr = 0; rr < 4; rr++)
            act[rr] = *(const float4*)(Xl + rr * 32 * xstride + kq * 4);
        #pragma unroll
        for (int k4 = 0; k4 < 4; ++k4) {
            const ulonglong2* wp = (const ulonglong2*)(Wp + (kq * 4 + k4) * 128 + w8);
            ulonglong2 wA = wp[0], wB = wp[1];
            #pragma unroll
            for (int rr = 0; rr < 4; rr++) {
                float a = (k4 == 0) ? act[rr].x : (k4 == 1) ? act[rr].y
                        : (k4 == 2) ? act[rr].z : act[rr].w;
                ull ap = pack2(a);
                fma2(acc[rr][0], ap, wA.x); fma2(acc[rr][1], ap, wA.y);
                fma2(acc[rr][2], ap, wB.x); fma2(acc[rr][3], ap, wB.y);
            }
        }
    }
}

__device__ __forceinline__ void ln_relu_q(ull acc[4][4],
    const float* __restrict__ b1, const float* __restrict__ gam, const float* __restrict__ bet,
    float* Hs, float* red, float* mus, float* rss, int tid, int l, int w)
{
    const int w8 = w * 8;
    float a1[4][8];
    #pragma unroll
    for (int r = 0; r < 4; r++) {
        float s = 0.f, s2 = 0.f;
        #pragma unroll
        for (int cp = 0; cp < 4; cp++) {
            float2 t = unpack2(acc[r][cp]);
            float x0 = t.x + b1[w8 + cp*2], x1 = t.y + b1[w8 + cp*2 + 1];
            a1[r][cp*2] = x0; a1[r][cp*2+1] = x1;
            s += x0 + x1; s2 += x0*x0 + x1*x1;
        }
        int row = r * 32 + l;
        red[row*17 + w] = s; red[2176 + row*17 + w] = s2;
    }
    __syncthreads();
    if (tid < 128) {
        float s = 0.f, s2 = 0.f;
        #pragma unroll
        for (int i = 0; i < 16; i++) { s += red[tid*17 + i]; s2 += red[2176 + tid*17 + i]; }
        float mu = s * (1.f/128.f);
        float var = fmaxf(s2 * (1.f/128.f) - mu*mu, 0.f);
        mus[tid] = mu; rss[tid] = rsqrtf(var + 1e-5f);
    }
    __syncthreads();
    #pragma unroll
    for (int r = 0; r < 4; r++) {
        int row = r * 32 + l;
        float mu = mus[row], rs = rss[row];
        float4 hv[2];
        #pragma unroll
        for (int c = 0; c < 8; c++) {
            float h = gam[w8 + c] * (a1[r][c] - mu) * rs + bet[w8 + c];
            ((float*)hv)[c] = fmaxf(h, 0.f);
        }
        float4* hp = (float4*)(Hs + row * 132 + w8);
        hp[0] = hv[0]; hp[1] = hv[1];
    }
}

__global__ void __launch_bounds__(NTQ, 1) q_mlp_kernel(const float* __restrict__ h_bond,
    const float* __restrict__ W1, const float* __restrict__ b1,
    const float* __restrict__ gam, const float* __restrict__ bet,
    const float* __restrict__ W2, const float* __restrict__ b2, int E)
{
    extern __shared__ float sm[];
    float* Xs  = sm;
    float* Hs  = Xs + 128*132;
    float* Wb  = Hs + 128*132;
    float* red = Wb + 2*4096;
    float* mus = red + 2*2176;
    float* rss = mus + 128;
    int tid = threadIdx.x, l = tid & 31, w = tid >> 5;
    const int w8 = w * 8;
    int e0 = blockIdx.x * 128;

    load_chunk_nc(W1, 128, 0, Wb + 0,    tid); CPC();
    load_chunk_nc(W1, 128, 1, Wb + 4096, tid); CPC();

    for (int v = tid; v < 128*32; v += NTQ) {
        int row = v >> 5, c4 = v & 31;
        float4 x = make_float4(0.f, 0.f, 0.f, 0.f);
        if (e0 + row < E) x = ((const float4*)h_bond)[(size_t)(e0 + row)*32 + c4];
        float* xr = Xs + row*132 + c4*4;
        xr[0] = x.x; xr[1] = x.y; xr[2] = x.z; xr[3] = x.w;
    }

    ull a1p[4][4];
    #pragma unroll
    for (int r = 0; r < 4; r++)
        #pragma unroll
        for (int c = 0; c < 4; c++) a1p[r][c] = 0ULL;
    const float* Xl = Xs + l * 132;
    for (int c = 0; c < 4; c++) {
        asm volatile("cp.async.wait_group 1;");
        __syncthreads();
        gemm_chunk(Xl + c*32, 132, Wb + (c & 1)*4096, w8, a1p);
        __syncthreads();
        if (c + 2 < 4) load_chunk_nc(W1, 128, c + 2, Wb + (c & 1)*4096, tid);
        CPC();
    }
    load_chunk_nc(W2, 128, 0, Wb + 0,    tid); CPC();
    load_chunk_nc(W2, 128, 1, Wb + 4096, tid); CPC();

    ln_relu_q(a1p, b1, gam, bet, Hs, red, mus, rss, tid, l, w);

    ull a2p[4][4];
    #pragma unroll
    for (int r = 0; r < 4; r++)
        #pragma unroll
        for (int c = 0; c < 4; c++) a2p[r][c] = 0ULL;
    const float* Hl = Hs + l * 132;
    for (int c = 0; c < 4; c++) {
        asm volatile("cp.async.wait_group 1;");
        __syncthreads();
        gemm_chunk(Hl + c*32, 132, Wb + (c & 1)*4096, w8, a2p);
        __syncthreads();
        if (c + 2 < 4) load_chunk_nc(W2, 128, c + 2, Wb + (c & 1)*4096, tid);
        CPC();
    }
    #pragma unroll
    for (int r = 0; r < 4; r++) {
        int row = r * 32 + l;
        int e = e0 + row;
        if (e < E) {
            float o[8];
            #pragma unroll
            for (int cp = 0; cp < 4; cp++) {
                float2 t = unpack2(a2p[r][cp]);
                o[cp*2] = t.x + b2[w8 + cp*2]; o[cp*2+1] = t.y + b2[w8 + cp*2 + 1];
            }
            float4* qp = (float4*)(g_q + (size_t)e*128 + w8);
            qp[0] = *(float4*)&o[0]; qp[1] = *(float4*)&o[4];
        }
    }
}

__global__ void edge_feat_kernel(const float* __restrict__ pos,
                                 const int* __restrict__ brow,
                                 const int* __restrict__ bcol, int E)
{
    int e = blockIdx.x * blockDim.x + threadIdx.x;
    if (e >= E) return;
    int r = brow[e], c = bcol[e];
    float dx = pos[c*3+0] - pos[r*3+0];
    float dy = pos[c*3+1] - pos[r*3+1];
    float dz = pos[c*3+2] - pos[r*3+2];
    float d  = sqrtf(dx*dx + dy*dy + dz*dz);
    const float step  = 10.0f / 19.0f;
    const float coeff = -0.5f / (step * step);
    #pragma unroll
    for (int g = 0; g < 20; ++g) {
        float t = d - step * (float)g;
        g_rfeat[e*20 + g] = expf(coeff * t * t);
    }
}

__global__ void attn_out_kernel(const int* __restrict__ idx_ji,
                                int T, int E, float* __restrict__ out)
{
    int warp = (blockIdx.x * blockDim.x + threadIdx.x) >> 5;
    int lane = threadIdx.x & 31;
    if (warp >= E) return;
    int e = warp;
    int lo = 0, hi = T;
    while (lo < hi) { int m = (lo + hi) >> 1; if (idx_ji[m] <  e)     lo = m + 1; else hi = m; }
    int s = lo;
    int hi2 = T;
    while (lo < hi2) { int m = (lo + hi2) >> 1; if (idx_ji[m] < e + 1) lo = m + 1; else hi2 = m; }
    int en = lo;
    int head = lane >> 1, half = lane & 1;
    float mx = -INFINITY;
    for (int t = s; t < en; t++) mx = fmaxf(mx, g_logits[(size_t)t*16 + head]);
    float den = 0.f, ax = 0.f, ay = 0.f, az = 0.f, aw = 0.f;
    for (int t = s; t < en; t++) {
        float w = expf(g_logits[(size_t)t*16 + head] - mx);
        den += w;
        float4 v = *(const float4*)(g_v + (size_t)t*128 + head*8 + half*4);
        ax += w*v.x; ay += w*v.y; az += w*v.z; aw += w*v.w;
    }
    float inv = (en > s) ? (1.f / den) : 0.f;
    *(float4*)(out + (size_t)e*128 + head*8 + half*4) =
        make_float4(ax*inv, ay*inv, az*inv, aw*inv);
}

// ---------------- launcher ----------------
extern "C" void kernel_launch(void* const* d_in, const int* in_sizes, int n_in,
                              void* d_out, int out_size)
{
    const float* h_bond = (const float*)d_in[1];
    const float* pos    = (const float*)d_in[2];
    const float* kW1 = (const float*)d_in[3];
    const float* kb1 = (const float*)d_in[4];
    const float* kg  = (const float*)d_in[5];
    const float* kb  = (const float*)d_in[6];
    const float* kW2 = (const float*)d_in[7];
    const float* kb2 = (const float*)d_in[8];
    const float* vW1 = (const float*)d_in[9];
    const float* vb1 = (const float*)d_in[10];
    const float* vg  = (const float*)d_in[11];
    const float* vb  = (const float*)d_in[12];
    const float* vW2 = (const float*)d_in[13];
    const float* vb2 = (const float*)d_in[14];
    const float* qW1 = (const float*)d_in[15];
    const float* qb1 = (const float*)d_in[16];
    const float* qg  = (const float*)d_in[17];
    const float* qb  = (const float*)d_in[18];
    const float* qW2 = (const float*)d_in[19];
    const float* qb2 = (const float*)d_in[20];
    const int* bond_row = (const int*)d_in[21];
    const int* bond_col = (const int*)d_in[22];
    const int* idx_i  = (const int*)d_in[23];
    const int* idx_j  = (const int*)d_in[24];
    const int* idx_k  = (const int*)d_in[25];
    const int* idx_kj = (const int*)d_in[26];
    const int* idx_ji = (const int*)d_in[27];
    int E = in_sizes[21];
    int T = in_sizes[23];

    const int SMEM_Q = (128*132 + 128*132 + 2*4096 + 2*2176 + 256) * 4;
    cudaFuncSetAttribute(q_mlp_kernel,      cudaFuncAttributeMaxDynamicSharedMemorySize, SMEM_Q);
    cudaFuncSetAttribute(triplet_mma_kernel, cudaFuncAttributeMaxDynamicSharedMemorySize, SMEM_T);

    int nb  = (T + 127) / 128;
    int nbA = nb / 2; if (nbA < 1) nbA = 1;
    int nbB = nb - nbA;

    prep_weights<<<80, 1024>>>(kW1, vW1, kW2, vW2);
    edge_feat_kernel<<<(E + 255) / 256, 256>>>(pos, bond_row, bond_col, E);
    q_mlp_kernel<<<(E + 127) / 128, NTQ, SMEM_Q>>>(h_bond, qW1, qb1, qg, qb, qW2, qb2, E);
    triplet_mma_kernel<<<nbA, 256, SMEM_T>>>(
        h_bond, pos, kb1, kg, kb, kb2, vb1, vg, vb, vb2,
        idx_i, idx_j, idx_k, idx_kj, idx_ji, 0, T);
    if (nbB > 0)
        triplet_mma_kernel<<<nbB, 256, SMEM_T>>>(
            h_bond, pos, kb1, kg, kb, kb2, vb1, vg, vb, vb2,
            idx_i, idx_j, idx_k, idx_kj, idx_ji, nbA, T);
    attn_out_kernel<<<(E * 32 + 255) / 256, 256>>>(idx_ji, T, E, (float*)d_out);
}

// round 13
// speedup vs baseline: 1.7628x; 1.0484x over previous
#include <cuda_runtime.h>
#include <cuda_fp16.h>
#include <math.h>
#include <stdint.h>

// ---------------------------------------------------------------------------
// BondUpdateLayer, round 13: HMMA m16n8k16 triplet MLPs (fp16-split fp32
// emulation, 3 passes) with 512-thread CTAs: warp = 16 rows x 64 cols
// (col-split pairs of warps) for 2x occupancy vs round 12. LN adds a tiny
// cross-half smem reduction. q_mlp/attn/edge unchanged.
// ---------------------------------------------------------------------------

#define EN    80000
#define TMAXN 640000
#define NTQ   512
#define NTT   512

typedef unsigned long long ull;

__device__ float g_rfeat [EN * 20];
__device__ float g_q     [EN * 128];
__device__ float g_logits[(size_t)TMAXN * 16];
__device__ float g_v     [(size_t)TMAXN * 128];
// fragment-packed weight words (half2 per word):
// kW1h@0, kW1l@12288, vW1h@24576, vW1l@36864 (12288 words each: 12 k16)
// kW2h@49152, kW2l@57344, vW2h@65536, vW2l@73728 (8192 words each: 8 k16)
__device__ __align__(16) uint32_t g_Bw[81920];

// ---------------- helpers ----------------
__device__ __forceinline__ ull pack2(float v) {
    ull r; asm("mov.b64 %0, {%1, %1};" : "=l"(r) : "f"(v)); return r;
}
__device__ __forceinline__ void fma2(ull& d, ull a, ull b) {
    asm("fma.rn.f32x2 %0, %1, %2, %0;" : "+l"(d) : "l"(a), "l"(b));
}
__device__ __forceinline__ float2 unpack2(ull v) {
    float lo, hi; asm("mov.b64 {%0, %1}, %2;" : "=f"(lo), "=f"(hi) : "l"(v));
    return make_float2(lo, hi);
}
__device__ __forceinline__ void split2(float f0, float f1, uint32_t& hi, uint32_t& lo) {
    __half h0 = __float2half_rn(f0), h1 = __float2half_rn(f1);
    __half l0 = __float2half_rn(f0 - __half2float(h0));
    __half l1 = __float2half_rn(f1 - __half2float(h1));
    __half2 H = __halves2half2(h0, h1), L = __halves2half2(l0, l1);
    hi = *(uint32_t*)&H; lo = *(uint32_t*)&L;
}
__device__ __forceinline__ void mma16816(float c[4], uint32_t a0, uint32_t a1,
                                         uint32_t a2, uint32_t a3,
                                         uint32_t b0, uint32_t b1) {
    asm volatile(
        "mma.sync.aligned.m16n8k16.row.col.f32.f16.f16.f32 "
        "{%0,%1,%2,%3},{%4,%5,%6,%7},{%8,%9},{%0,%1,%2,%3};"
        : "+f"(c[0]), "+f"(c[1]), "+f"(c[2]), "+f"(c[3])
        : "r"(a0), "r"(a1), "r"(a2), "r"(a3), "r"(b0), "r"(b1));
}

// ---------------- weight prep: pack into fragment order ----------------
// word layout per image: idx = ((k16*16 + n8)*32 + lane)*2 + r
// b0(r=0): halves W[k16*16 + (lane&3)*2 + {0,1}][n8*8 + (lane>>2)]
// b1(r=1): same with k += 8
__global__ void prep_weights(const float* __restrict__ kW1, const float* __restrict__ vW1,
                             const float* __restrict__ kW2, const float* __restrict__ vW2)
{
    int word = blockIdx.x * 1024 + threadIdx.x;
    const float* W; int kdim, rem; bool lo;
    if (word < 49152) {
        int img = word / 12288; rem = word % 12288;
        W = (img < 2) ? kW1 : vW1; lo = img & 1; kdim = 181;
    } else {
        int w2 = word - 49152;
        int img = w2 / 8192; rem = w2 % 8192;
        W = (img < 2) ? kW2 : vW2; lo = img & 1; kdim = 128;
    }
    int r = rem & 1, lane = (rem >> 1) & 31, n8 = (rem >> 6) & 15, k16 = rem >> 10;
    int K = k16 * 16 + (lane & 3) * 2 + r * 8;
    int n = n8 * 8 + (lane >> 2);
    float w0 = (K     < kdim) ? W[(size_t)K * 128 + n]       : 0.f;
    float w1 = (K + 1 < kdim) ? W[(size_t)(K + 1) * 128 + n] : 0.f;
    __half h0 = __float2half_rn(w0), h1 = __float2half_rn(w1);
    if (lo) {
        h0 = __float2half_rn(w0 - __half2float(h0));
        h1 = __float2half_rn(w1 - __half2float(h1));
    }
    __half2 p = __halves2half2(h0, h1);
    g_Bw[word] = *(uint32_t*)&p;
}

// ---------------- weight chunk loader: 2 k16 (hi 2048 w + lo 2048 w) ----------
__device__ __forceinline__ void load_wc(const uint32_t* __restrict__ gHi,
                                        const uint32_t* __restrict__ gLo,
                                        int c, uint32_t* dst, int tid)
{
    #pragma unroll
    for (int i = 0; i < 2; i++) {
        int v = tid + i * NTT;   // 0..1023 float4 slots
        const uint32_t* src = (v < 512) ? (gHi + c * 2048 + v * 4)
                                        : (gLo + c * 2048 + (v - 512) * 4);
        unsigned sa = (unsigned)__cvta_generic_to_shared(dst + v * 4);
        asm volatile("cp.async.cg.shared.global [%0], [%1], 16;" :: "r"(sa), "l"(src));
    }
}
#define CPC() asm volatile("cp.async.commit_group;")

// ---------------- one GEMM phase: acc += Ah@(Wh+Wl) + Al@Wh ----------------
// warp covers rows [R0 base] x cols [n8base*8, n8base*8+64)
__device__ __forceinline__ void gemm_phase(
    float acc[8][4], const __half* __restrict__ Ah, const __half* __restrict__ Al,
    int astride, int nk16,
    const uint32_t* __restrict__ gHi, const uint32_t* __restrict__ gLo,
    uint32_t* Wbuf, int R0, int t2, int lane, int n8base, int tid)
{
    load_wc(gHi, gLo, 0, Wbuf, tid);        CPC();
    load_wc(gHi, gLo, 1, Wbuf + 4096, tid); CPC();
    int nch = nk16 >> 1;
    for (int c = 0; c < nch; c++) {
        asm volatile("cp.async.wait_group 1;");
        __syncthreads();
        const uint32_t* WB = Wbuf + (c & 1) * 4096;
        #pragma unroll
        for (int kl = 0; kl < 2; kl++) {
            int cb = (c * 2 + kl) * 16 + t2;
            const __half* xh = Ah + R0 * astride + cb;
            uint32_t a0 = *(const uint32_t*)(xh);
            uint32_t a1 = *(const uint32_t*)(xh + 8 * astride);
            uint32_t a2 = *(const uint32_t*)(xh + 8);
            uint32_t a3 = *(const uint32_t*)(xh + 8 * astride + 8);
            const uint32_t* bh = WB + kl * 1024 + lane * 2 + n8base * 64;
            #pragma unroll
            for (int n8 = 0; n8 < 8; n8++) {
                ull b = *(const ull*)(bh + n8 * 64);
                mma16816(acc[n8], a0, a1, a2, a3, (uint32_t)b, (uint32_t)(b >> 32));
            }
            const uint32_t* bl = bh + 2048;
            #pragma unroll
            for (int n8 = 0; n8 < 8; n8++) {
                ull b = *(const ull*)(bl + n8 * 64);
                mma16816(acc[n8], a0, a1, a2, a3, (uint32_t)b, (uint32_t)(b >> 32));
            }
            const __half* xl = Al + R0 * astride + cb;
            uint32_t l0 = *(const uint32_t*)(xl);
            uint32_t l1 = *(const uint32_t*)(xl + 8 * astride);
            uint32_t l2 = *(const uint32_t*)(xl + 8);
            uint32_t l3 = *(const uint32_t*)(xl + 8 * astride + 8);
            #pragma unroll
            for (int n8 = 0; n8 < 8; n8++) {
                ull b = *(const ull*)(bh + n8 * 64);
                mma16816(acc[n8], l0, l1, l2, l3, (uint32_t)b, (uint32_t)(b >> 32));
            }
        }
        __syncthreads();
        if (c + 2 < nch) load_wc(gHi, gLo, c + 2, Wbuf + (c & 1) * 4096, tid);
        CPC();
    }
}

// ---------------- LN + ReLU + split-store (cross-half smem reduction) --------
__device__ __forceinline__ void ln_store(float acc[8][4],
    const float* __restrict__ gam, const float* __restrict__ bet,
    __half* HH, __half* HL, float* sred, float* qred,
    int R0, int t2, int half_id, int n8base)
{
    float s0 = 0.f, q0 = 0.f, s1 = 0.f, q1 = 0.f;
    #pragma unroll
    for (int n8 = 0; n8 < 8; n8++) {
        s0 += acc[n8][0] + acc[n8][1];
        q0 += acc[n8][0]*acc[n8][0] + acc[n8][1]*acc[n8][1];
        s1 += acc[n8][2] + acc[n8][3];
        q1 += acc[n8][2]*acc[n8][2] + acc[n8][3]*acc[n8][3];
    }
    #pragma unroll
    for (int o = 1; o < 4; o <<= 1) {
        s0 += __shfl_xor_sync(0xffffffffu, s0, o);
        q0 += __shfl_xor_sync(0xffffffffu, q0, o);
        s1 += __shfl_xor_sync(0xffffffffu, s1, o);
        q1 += __shfl_xor_sync(0xffffffffu, q1, o);
    }
    int R1 = R0 + 8;
    // partials over this warp's 64 cols
    sred[R0 * 2 + half_id] = s0; qred[R0 * 2 + half_id] = q0;
    sred[R1 * 2 + half_id] = s1; qred[R1 * 2 + half_id] = q1;
    __syncthreads();
    float S0 = sred[R0*2] + sred[R0*2+1], Q0 = qred[R0*2] + qred[R0*2+1];
    float S1 = sred[R1*2] + sred[R1*2+1], Q1 = qred[R1*2] + qred[R1*2+1];
    float mu0 = S0 * (1.f/128.f), mu1 = S1 * (1.f/128.f);
    float rs0 = rsqrtf(fmaxf(Q0 * (1.f/128.f) - mu0*mu0, 0.f) + 1e-5f);
    float rs1 = rsqrtf(fmaxf(Q1 * (1.f/128.f) - mu1*mu1, 0.f) + 1e-5f);
    #pragma unroll
    for (int n8 = 0; n8 < 8; n8++) {
        int col = (n8base + n8) * 8 + t2;
        float g0 = gam[col], g1 = gam[col+1], b0 = bet[col], b1 = bet[col+1];
        float h00 = fmaxf(g0 * (acc[n8][0] - mu0) * rs0 + b0, 0.f);
        float h01 = fmaxf(g1 * (acc[n8][1] - mu0) * rs0 + b1, 0.f);
        float h10 = fmaxf(g0 * (acc[n8][2] - mu1) * rs1 + b0, 0.f);
        float h11 = fmaxf(g1 * (acc[n8][3] - mu1) * rs1 + b1, 0.f);
        uint32_t hi, lo;
        split2(h00, h01, hi, lo);
        *(uint32_t*)(HH + R0 * 136 + col) = hi;
        *(uint32_t*)(HL + R0 * 136 + col) = lo;
        split2(h10, h11, hi, lo);
        *(uint32_t*)(HH + R1 * 136 + col) = hi;
        *(uint32_t*)(HL + R1 * 136 + col) = lo;
    }
}

// ---------------- triplet kernel ----------------
// smem (bytes): XH 0(51200) XL 51200(51200) HH 102400(34816) HL 137216(34816)
// Wbuf 172032(32768) bias 204800(4096) kjS 208896(512) jiS 209408(512)
// sred 209920(1024) qred 210944(1024) = 211968
#define SMEM_T 211968

__global__ void __launch_bounds__(NTT, 1) triplet_mma_kernel(
    const float* __restrict__ h_bond, const float* __restrict__ pos,
    const float* __restrict__ kb1, const float* __restrict__ kg,
    const float* __restrict__ kb,  const float* __restrict__ kb2,
    const float* __restrict__ vb1, const float* __restrict__ vg,
    const float* __restrict__ vb,  const float* __restrict__ vb2,
    const int* __restrict__ idx_i, const int* __restrict__ idx_j,
    const int* __restrict__ idx_k, const int* __restrict__ idx_kj,
    const int* __restrict__ idx_ji, int blk0, int T)
{
    extern __shared__ char smem[];
    __half* XH = (__half*)(smem);
    __half* XL = (__half*)(smem + 51200);
    __half* HH = (__half*)(smem + 102400);
    __half* HL = (__half*)(smem + 137216);
    uint32_t* Wbuf = (uint32_t*)(smem + 172032);
    float* bias = (float*)(smem + 204800);
    int* kjS = (int*)(smem + 208896);
    int* jiS = (int*)(smem + 209408);
    float* sred = (float*)(smem + 209920);
    float* qred = (float*)(smem + 210944);

    int tid = threadIdx.x, lane = tid & 31, w = tid >> 5;
    int g = lane >> 2, t2 = (lane & 3) * 2;
    int R0 = (w & 7) * 16 + g, R1 = R0 + 8;
    int half_id = w >> 3;            // 0: cols 0..63, 1: cols 64..127
    int n8base = half_id * 8;
    int t0 = (blockIdx.x + blk0) * 128;

    // zero XH+XL (102400 B = 6400 uint4)
    for (int v = tid; v < 6400; v += NTT)
        ((uint4*)smem)[v] = make_uint4(0, 0, 0, 0);
    {
        const float* srcs[8] = {kb1, kg, kb, kb2, vb1, vg, vb, vb2};
        for (int v = tid; v < 1024; v += NTT) bias[v] = srcs[v >> 7][v & 127];
    }
    __syncthreads();

    // indices + angular features (cols 168..181)
    if (tid < 128) {
        int t = t0 + tid;
        int kj = -1, ji = -1;
        float vals[14];
        #pragma unroll
        for (int p = 0; p < 14; p++) vals[p] = 0.f;
        if (t < T) {
            kj = idx_kj[t]; ji = idx_ji[t];
            int ii = idx_i[t], jj = idx_j[t], kk = idx_k[t];
            float pix = pos[ii*3+0], piy = pos[ii*3+1], piz = pos[ii*3+2];
            float jx = pos[jj*3+0]-pix, jy = pos[jj*3+1]-piy, jz = pos[jj*3+2]-piz;
            float kx = pos[kk*3+0]-pix, ky = pos[kk*3+1]-piy, kz = pos[kk*3+2]-piz;
            float dt = jx*kx + jy*ky + jz*kz;
            float cx = jy*kz - jz*ky, cy = jz*kx - jx*kz, cz = jx*ky - jy*kx;
            float cr = sqrtf(cx*cx + cy*cy + cz*cz);
            float ang = atan2f(cr, dt);
            vals[0] = ang;
            const float fq[6] = {1.f, 2.f, 3.f, 1.f, 0.5f, 1.f/3.f};
            #pragma unroll
            for (int i = 0; i < 6; i++) {
                vals[1 + i] = sinf(ang * fq[i]);
                vals[7 + i] = cosf(ang * fq[i]);
            }
        }
        kjS[tid] = kj; jiS[tid] = ji;
        #pragma unroll
        for (int p = 0; p < 7; p++) {
            uint32_t hi, lo;
            split2(vals[2*p], vals[2*p+1], hi, lo);
            *(uint32_t*)(XH + tid * 200 + 168 + 2*p) = hi;
            *(uint32_t*)(XL + tid * 200 + 168 + 2*p) = lo;
        }
    }
    __syncthreads();

    // h_bond[idx_kj] -> cols 0..127
    for (int v = tid; v < 128 * 32; v += NTT) {
        int row = v >> 5, c4 = v & 31;
        int kj = kjS[row];
        if (kj >= 0) {
            float4 x = ((const float4*)h_bond)[(size_t)kj * 32 + c4];
            uint32_t h0, l0, h1, l1;
            split2(x.x, x.y, h0, l0); split2(x.z, x.w, h1, l1);
            *(uint2*)(XH + row * 200 + c4 * 4) = make_uint2(h0, h1);
            *(uint2*)(XL + row * 200 + c4 * 4) = make_uint2(l0, l1);
        }
    }
    // rfeat -> cols 128..147 (kj), 148..167 (ji)
    for (int v = tid; v < 128 * 20; v += NTT) {
        int row = v / 20, u = v % 20;
        float f0 = 0.f, f1 = 0.f; int col; bool ok = false;
        if (u < 10) {
            int kj = kjS[row]; col = 128 + 2 * u;
            if (kj >= 0) { f0 = g_rfeat[kj*20 + 2*u]; f1 = g_rfeat[kj*20 + 2*u + 1]; ok = true; }
        } else {
            int j = u - 10, ji = jiS[row]; col = 148 + 2 * j;
            if (ji >= 0) { f0 = g_rfeat[ji*20 + 2*j]; f1 = g_rfeat[ji*20 + 2*j + 1]; ok = true; }
        }
        if (ok) {
            uint32_t hi, lo;
            split2(f0, f1, hi, lo);
            *(uint32_t*)(XH + row * 200 + col) = hi;
            *(uint32_t*)(XL + row * 200 + col) = lo;
        }
    }
    __syncthreads();

    float acc[8][4];

    // ======== k-MLP ========
    #pragma unroll
    for (int n8 = 0; n8 < 8; n8++) {
        acc[n8][0] = bias[0*128 + (n8base + n8)*8 + t2];
        acc[n8][1] = bias[0*128 + (n8base + n8)*8 + t2 + 1];
        acc[n8][2] = acc[n8][0];
        acc[n8][3] = acc[n8][1];
    }
    gemm_phase(acc, XH, XL, 200, 12, g_Bw + 0, g_Bw + 12288, Wbuf, R0, t2, lane, n8base, tid);
    ln_store(acc, bias + 128, bias + 256, HH, HL, sred, qred, R0, t2, half_id, n8base);
    __syncthreads();

    #pragma unroll
    for (int n8 = 0; n8 < 8; n8++) {
        acc[n8][0] = bias[3*128 + (n8base + n8)*8 + t2];
        acc[n8][1] = bias[3*128 + (n8base + n8)*8 + t2 + 1];
        acc[n8][2] = acc[n8][0];
        acc[n8][3] = acc[n8][1];
    }
    gemm_phase(acc, HH, HL, 136, 8, g_Bw + 49152, g_Bw + 57344, Wbuf, R0, t2, lane, n8base, tid);

    // logits epilogue (head = global n8 index; warp-local)
    {
        int ji0 = jiS[R0], ji1 = jiS[R1];
        float lg0[8], lg1[8];
        #pragma unroll
        for (int n8 = 0; n8 < 8; n8++) { lg0[n8] = 0.f; lg1[n8] = 0.f; }
        if (ji0 >= 0) {
            #pragma unroll
            for (int n8 = 0; n8 < 8; n8++) {
                float2 qv = *(const float2*)(g_q + (size_t)ji0 * 128 + (n8base + n8) * 8 + t2);
                lg0[n8] = acc[n8][0] * qv.x + acc[n8][1] * qv.y;
            }
        }
        if (ji1 >= 0) {
            #pragma unroll
            for (int n8 = 0; n8 < 8; n8++) {
                float2 qv = *(const float2*)(g_q + (size_t)ji1 * 128 + (n8base + n8) * 8 + t2);
                lg1[n8] = acc[n8][2] * qv.x + acc[n8][3] * qv.y;
            }
        }
        #pragma unroll
        for (int o = 1; o < 4; o <<= 1)
            #pragma unroll
            for (int n8 = 0; n8 < 8; n8++) {
                lg0[n8] += __shfl_xor_sync(0xffffffffu, lg0[n8], o);
                lg1[n8] += __shfl_xor_sync(0xffffffffu, lg1[n8], o);
            }
        const float sc = 0.3535533905932738f;
        int tq = lane & 3;  // lane writes heads n8base + 2*tq, +1
        if (ji0 >= 0)
            *(float2*)(g_logits + (size_t)(t0 + R0) * 16 + n8base + 2 * tq) =
                make_float2(lg0[2*tq] * sc, lg0[2*tq+1] * sc);
        if (ji1 >= 0)
            *(float2*)(g_logits + (size_t)(t0 + R1) * 16 + n8base + 2 * tq) =
                make_float2(lg1[2*tq] * sc, lg1[2*tq+1] * sc);
    }

    // ======== v-MLP ========
    #pragma unroll
    for (int n8 = 0; n8 < 8; n8++) {
        acc[n8][0] = bias[4*128 + (n8base + n8)*8 + t2];
        acc[n8][1] = bias[4*128 + (n8base + n8)*8 + t2 + 1];
        acc[n8][2] = acc[n8][0];
        acc[n8][3] = acc[n8][1];
    }
    gemm_phase(acc, XH, XL, 200, 12, g_Bw + 24576, g_Bw + 36864, Wbuf, R0, t2, lane, n8base, tid);
    __syncthreads();
    ln_store(acc, bias + 5*128, bias + 6*128, HH, HL, sred, qred, R0, t2, half_id, n8base);
    __syncthreads();

    #pragma unroll
    for (int n8 = 0; n8 < 8; n8++) {
        acc[n8][0] = bias[7*128 + (n8base + n8)*8 + t2];
        acc[n8][1] = bias[7*128 + (n8base + n8)*8 + t2 + 1];
        acc[n8][2] = acc[n8][0];
        acc[n8][3] = acc[n8][1];
    }
    gemm_phase(acc, HH, HL, 136, 8, g_Bw + 65536, g_Bw + 73728, Wbuf, R0, t2, lane, n8base, tid);

    // V epilogue
    {
        int ji0 = jiS[R0], ji1 = jiS[R1];
        #pragma unroll
        for (int n8 = 0; n8 < 8; n8++) {
            int col = (n8base + n8) * 8 + t2;
            if (ji0 >= 0)
                *(float2*)(g_v + (size_t)(t0 + R0) * 128 + col) =
                    make_float2(acc[n8][0], acc[n8][1]);
            if (ji1 >= 0)
                *(float2*)(g_v + (size_t)(t0 + R1) * 128 + col) =
                    make_float2(acc[n8][2], acc[n8][3]);
        }
    }
}

// ======================= r9 SIMT kernels (q/edge/attn) ==================
__device__ __forceinline__ void load_chunk_nc(const float* __restrict__ W, int kdim,
                                              int c, float* dst, int tid)
{
    #pragma unroll
    for (int i = 0; i < 2; i++) {
        int v = tid + i * NTQ;
        int krow = c * 32 + (v >> 5);
        float* d = dst + v * 4;
        if (krow < kdim) {
            unsigned sa = (unsigned)__cvta_generic_to_shared(d);
            const float* s = W + (size_t)krow * 128 + (v & 31) * 4;
            asm volatile("cp.async.cg.shared.global [%0], [%1], 16;" :: "r"(sa), "l"(s));
        } else { d[0]=0.f; d[1]=0.f; d[2]=0.f; d[3]=0.f; }
    }
}

__device__ __forceinline__ void gemm_chunk(const float* __restrict__ Xl, int xstride,
                                           const float* __restrict__ Wp, int w8, ull acc[4][4])
{
    #pragma unroll
    for (int kq = 0; kq < 8; ++kq) {
        float4 act[4];
        #pragma unroll
        for (int rr = 0; rr < 4; rr++)
            act[rr] = *(const float4*)(Xl + rr * 32 * xstride + kq * 4);
        #pragma unroll
        for (int k4 = 0; k4 < 4; ++k4) {
            const ulonglong2* wp = (const ulonglong2*)(Wp + (kq * 4 + k4) * 128 + w8);
            ulonglong2 wA = wp[0], wB = wp[1];
            #pragma unroll
            for (int rr = 0; rr < 4; rr++) {
                float a = (k4 == 0) ? act[rr].x : (k4 == 1) ? act[rr].y
                        : (k4 == 2) ? act[rr].z : act[rr].w;
                ull ap = pack2(a);
                fma2(acc[rr][0], ap, wA.x); fma2(acc[rr][1], ap, wA.y);
                fma2(acc[rr][2], ap, wB.x); fma2(acc[rr][3], ap, wB.y);
            }
        }
    }
}

__device__ __forceinline__ void ln_relu_q(ull acc[4][4],
    const float* __restrict__ b1, const float* __restrict__ gam, const float* __restrict__ bet,
    float* Hs, float* red, float* mus, float* rss, int tid, int l, int w)
{
    const int w8 = w * 8;
    float a1[4][8];
    #pragma unroll
    for (int r = 0; r < 4; r++) {
        float s = 0.f, s2 = 0.f;
        #pragma unroll
        for (int cp = 0; cp < 4; cp++) {
            float2 t = unpack2(acc[r][cp]);
            float x0 = t.x + b1[w8 + cp*2], x1 = t.y + b1[w8 + cp*2 + 1];
            a1[r][cp*2] = x0; a1[r][cp*2+1] = x1;
            s += x0 + x1; s2 += x0*x0 + x1*x1;
        }
        int row = r * 32 + l;
        red[row*17 + w] = s; red[2176 + row*17 + w] = s2;
    }
    __syncthreads();
    if (tid < 128) {
        float s = 0.f, s2 = 0.f;
        #pragma unroll
        for (int i = 0; i < 16; i++) { s += red[tid*17 + i]; s2 += red[2176 + tid*17 + i]; }
        float mu = s * (1.f/128.f);
        float var = fmaxf(s2 * (1.f/128.f) - mu*mu, 0.f);
        mus[tid] = mu; rss[tid] = rsqrtf(var + 1e-5f);
    }
    __syncthreads();
    #pragma unroll
    for (int r = 0; r < 4; r++) {
        int row = r * 32 + l;
        float mu = mus[row], rs = rss[row];
        float4 hv[2];
        #pragma unroll
        for (int c = 0; c < 8; c++) {
            float h = gam[w8 + c] * (a1[r][c] - mu) * rs + bet[w8 + c];
            ((float*)hv)[c] = fmaxf(h, 0.f);
        }
        float4* hp = (float4*)(Hs + row * 132 + w8);
        hp[0] = hv[0]; hp[1] = hv[1];
    }
}

__global__ void __launch_bounds__(NTQ, 1) q_mlp_kernel(const float* __restrict__ h_bond,
    const float* __restrict__ W1, const float* __restrict__ b1,
    const float* __restrict__ gam, const float* __restrict__ bet,
    const float* __restrict__ W2, const float* __restrict__ b2, int E)
{
    extern __shared__ float sm[];
    float* Xs  = sm;
    float* Hs  = Xs + 128*132;
    float* Wb  = Hs + 128*132;
    float* red = Wb + 2*4096;
    float* mus = red + 2*2176;
    float* rss = mus + 128;
    int tid = threadIdx.x, l = tid & 31, w = tid >> 5;
    const int w8 = w * 8;
    int e0 = blockIdx.x * 128;

    load_chunk_nc(W1, 128, 0, Wb + 0,    tid); CPC();
    load_chunk_nc(W1, 128, 1, Wb + 4096, tid); CPC();

    for (int v = tid; v < 128*32; v += NTQ) {
        int row = v >> 5, c4 = v & 31;
        float4 x = make_float4(0.f, 0.f, 0.f, 0.f);
        if (e0 + row < E) x = ((const float4*)h_bond)[(size_t)(e0 + row)*32 + c4];
        float* xr = Xs + row*132 + c4*4;
        xr[0] = x.x; xr[1] = x.y; xr[2] = x.z; xr[3] = x.w;
    }

    ull a1p[4][4];
    #pragma unroll
    for (int r = 0; r < 4; r++)
        #pragma unroll
        for (int c = 0; c < 4; c++) a1p[r][c] = 0ULL;
    const float* Xl = Xs + l * 132;
    for (int c = 0; c < 4; c++) {
        asm volatile("cp.async.wait_group 1;");
        __syncthreads();
        gemm_chunk(Xl + c*32, 132, Wb + (c & 1)*4096, w8, a1p);
        __syncthreads();
        if (c + 2 < 4) load_chunk_nc(W1, 128, c + 2, Wb + (c & 1)*4096, tid);
        CPC();
    }
    load_chunk_nc(W2, 128, 0, Wb + 0,    tid); CPC();
    load_chunk_nc(W2, 128, 1, Wb + 4096, tid); CPC();

    ln_relu_q(a1p, b1, gam, bet, Hs, red, mus, rss, tid, l, w);

    ull a2p[4][4];
    #pragma unroll
    for (int r = 0; r < 4; r++)
        #pragma unroll
        for (int c = 0; c < 4; c++) a2p[r][c] = 0ULL;
    const float* Hl = Hs + l * 132;
    for (int c = 0; c < 4; c++) {
        asm volatile("cp.async.wait_group 1;");
        __syncthreads();
        gemm_chunk(Hl + c*32, 132, Wb + (c & 1)*4096, w8, a2p);
        __syncthreads();
        if (c + 2 < 4) load_chunk_nc(W2, 128, c + 2, Wb + (c & 1)*4096, tid);
        CPC();
    }
    #pragma unroll
    for (int r = 0; r < 4; r++) {
        int row = r * 32 + l;
        int e = e0 + row;
        if (e < E) {
            float o[8];
            #pragma unroll
            for (int cp = 0; cp < 4; cp++) {
                float2 t = unpack2(a2p[r][cp]);
                o[cp*2] = t.x + b2[w8 + cp*2]; o[cp*2+1] = t.y + b2[w8 + cp*2 + 1];
            }
            float4* qp = (float4*)(g_q + (size_t)e*128 + w8);
            qp[0] = *(float4*)&o[0]; qp[1] = *(float4*)&o[4];
        }
    }
}

__global__ void edge_feat_kernel(const float* __restrict__ pos,
                                 const int* __restrict__ brow,
                                 const int* __restrict__ bcol, int E)
{
    int e = blockIdx.x * blockDim.x + threadIdx.x;
    if (e >= E) return;
    int r = brow[e], c = bcol[e];
    float dx = pos[c*3+0] - pos[r*3+0];
    float dy = pos[c*3+1] - pos[r*3+1];
    float dz = pos[c*3+2] - pos[r*3+2];
    float d  = sqrtf(dx*dx + dy*dy + dz*dz);
    const float step  = 10.0f / 19.0f;
    const float coeff = -0.5f / (step * step);
    #pragma unroll
    for (int g = 0; g < 20; ++g) {
        float t = d - step * (float)g;
        g_rfeat[e*20 + g] = expf(coeff * t * t);
    }
}

__global__ void attn_out_kernel(const int* __restrict__ idx_ji,
                                int T, int E, float* __restrict__ out)
{
    int warp = (blockIdx.x * blockDim.x + threadIdx.x) >> 5;
    int lane = threadIdx.x & 31;
    if (warp >= E) return;
    int e = warp;
    int lo = 0, hi = T;
    while (lo < hi) { int m = (lo + hi) >> 1; if (idx_ji[m] <  e)     lo = m + 1; else hi = m; }
    int s = lo;
    int hi2 = T;
    while (lo < hi2) { int m = (lo + hi2) >> 1; if (idx_ji[m] < e + 1) lo = m + 1; else hi2 = m; }
    int en = lo;
    int head = lane >> 1, half = lane & 1;
    float mx = -INFINITY;
    for (int t = s; t < en; t++) mx = fmaxf(mx, g_logits[(size_t)t*16 + head]);
    float den = 0.f, ax = 0.f, ay = 0.f, az = 0.f, aw = 0.f;
    for (int t = s; t < en; t++) {
        float w = expf(g_logits[(size_t)t*16 + head] - mx);
        den += w;
        float4 v = *(const float4*)(g_v + (size_t)t*128 + head*8 + half*4);
        ax += w*v.x; ay += w*v.y; az += w*v.z; aw += w*v.w;
    }
    float inv = (en > s) ? (1.f / den) : 0.f;
    *(float4*)(out + (size_t)e*128 + head*8 + half*4) =
        make_float4(ax*inv, ay*inv, az*inv, aw*inv);
}

// ---------------- launcher ----------------
extern "C" void kernel_launch(void* const* d_in, const int* in_sizes, int n_in,
                              void* d_out, int out_size)
{
    const float* h_bond = (const float*)d_in[1];
    const float* pos    = (const float*)d_in[2];
    const float* kW1 = (const float*)d_in[3];
    const float* kb1 = (const float*)d_in[4];
    const float* kg  = (const float*)d_in[5];
    const float* kb  = (const float*)d_in[6];
    const float* kW2 = (const float*)d_in[7];
    const float* kb2 = (const float*)d_in[8];
    const float* vW1 = (const float*)d_in[9];
    const float* vb1 = (const float*)d_in[10];
    const float* vg  = (const float*)d_in[11];
    const float* vb  = (const float*)d_in[12];
    const float* vW2 = (const float*)d_in[13];
    const float* vb2 = (const float*)d_in[14];
    const float* qW1 = (const float*)d_in[15];
    const float* qb1 = (const float*)d_in[16];
    const float* qg  = (const float*)d_in[17];
    const float* qb  = (const float*)d_in[18];
    const float* qW2 = (const float*)d_in[19];
    const float* qb2 = (const float*)d_in[20];
    const int* bond_row = (const int*)d_in[21];
    const int* bond_col = (const int*)d_in[22];
    const int* idx_i  = (const int*)d_in[23];
    const int* idx_j  = (const int*)d_in[24];
    const int* idx_k  = (const int*)d_in[25];
    const int* idx_kj = (const int*)d_in[26];
    const int* idx_ji = (const int*)d_in[27];
    int E = in_sizes[21];
    int T = in_sizes[23];

    const int SMEM_Q = (128*132 + 128*132 + 2*4096 + 2*2176 + 256) * 4;
    cudaFuncSetAttribute(q_mlp_kernel,       cudaFuncAttributeMaxDynamicSharedMemorySize, SMEM_Q);
    cudaFuncSetAttribute(triplet_mma_kernel, cudaFuncAttributeMaxDynamicSharedMemorySize, SMEM_T);

    int nb  = (T + 127) / 128;
    int nbA = nb / 2; if (nbA < 1) nbA = 1;
    int nbB = nb - nbA;

    prep_weights<<<80, 1024>>>(kW1, vW1, kW2, vW2);
    edge_feat_kernel<<<(E + 255) / 256, 256>>>(pos, bond_row, bond_col, E);
    q_mlp_kernel<<<(E + 127) / 128, NTQ, SMEM_Q>>>(h_bond, qW1, qb1, qg, qb, qW2, qb2, E);
    triplet_mma_kernel<<<nbA, NTT, SMEM_T>>>(
        h_bond, pos, kb1, kg, kb, kb2, vb1, vg, vb, vb2,
        idx_i, idx_j, idx_k, idx_kj, idx_ji, 0, T);
    if (nbB > 0)
        triplet_mma_kernel<<<nbB, NTT, SMEM_T>>>(
            h_bond, pos, kb1, kg, kb, kb2, vb1, vg, vb, vb2,
            idx_i, idx_j, idx_k, idx_kj, idx_ji, nbA, T);
    attn_out_kernel<<<(E * 32 + 255) / 256, 256>>>(idx_ji, T, E, (float*)d_out);
}

// round 14
// speedup vs baseline: 2.0586x; 1.1678x over previous
#include <cuda_runtime.h>
#include <cuda_fp16.h>
#include <math.h>
#include <stdint.h>

// ---------------------------------------------------------------------------
// BondUpdateLayer, round 14: HMMA m16n8k16 triplet MLPs, 2-pass fp16-split
// emulation (xh*wh + xh*wl; activation-lo pass dropped -> 33% fewer MMAs,
// fallback-HMMA pipe rate is the wall). 512-thread CTAs, warp = 16 rows x
// 64 cols. q_mlp/attn/edge unchanged.
// ---------------------------------------------------------------------------

#define EN    80000
#define TMAXN 640000
#define NTQ   512
#define NTT   512

typedef unsigned long long ull;

__device__ float g_rfeat [EN * 20];
__device__ float g_q     [EN * 128];
__device__ float g_logits[(size_t)TMAXN * 16];
__device__ float g_v     [(size_t)TMAXN * 128];
// fragment-packed weight words (half2 per word):
// kW1h@0, kW1l@12288, vW1h@24576, vW1l@36864 (12288 words each: 12 k16)
// kW2h@49152, kW2l@57344, vW2h@65536, vW2l@73728 (8192 words each: 8 k16)
__device__ __align__(16) uint32_t g_Bw[81920];

// ---------------- helpers ----------------
__device__ __forceinline__ ull pack2(float v) {
    ull r; asm("mov.b64 %0, {%1, %1};" : "=l"(r) : "f"(v)); return r;
}
__device__ __forceinline__ void fma2(ull& d, ull a, ull b) {
    asm("fma.rn.f32x2 %0, %1, %2, %0;" : "+l"(d) : "l"(a), "l"(b));
}
__device__ __forceinline__ float2 unpack2(ull v) {
    float lo, hi; asm("mov.b64 {%0, %1}, %2;" : "=f"(lo), "=f"(hi) : "l"(v));
    return make_float2(lo, hi);
}
__device__ __forceinline__ uint32_t packh2(float f0, float f1) {
    __half2 H = __floats2half2_rn(f0, f1);
    return *(uint32_t*)&H;
}
__device__ __forceinline__ void mma16816(float c[4], uint32_t a0, uint32_t a1,
                                         uint32_t a2, uint32_t a3,
                                         uint32_t b0, uint32_t b1) {
    asm volatile(
        "mma.sync.aligned.m16n8k16.row.col.f32.f16.f16.f32 "
        "{%0,%1,%2,%3},{%4,%5,%6,%7},{%8,%9},{%0,%1,%2,%3};"
        : "+f"(c[0]), "+f"(c[1]), "+f"(c[2]), "+f"(c[3])
        : "r"(a0), "r"(a1), "r"(a2), "r"(a3), "r"(b0), "r"(b1));
}

// ---------------- weight prep: pack into fragment order ----------------
__global__ void prep_weights(const float* __restrict__ kW1, const float* __restrict__ vW1,
                             const float* __restrict__ kW2, const float* __restrict__ vW2)
{
    int word = blockIdx.x * 1024 + threadIdx.x;
    const float* W; int kdim, rem; bool lo;
    if (word < 49152) {
        int img = word / 12288; rem = word % 12288;
        W = (img < 2) ? kW1 : vW1; lo = img & 1; kdim = 181;
    } else {
        int w2 = word - 49152;
        int img = w2 / 8192; rem = w2 % 8192;
        W = (img < 2) ? kW2 : vW2; lo = img & 1; kdim = 128;
    }
    int r = rem & 1, lane = (rem >> 1) & 31, n8 = (rem >> 6) & 15, k16 = rem >> 10;
    int K = k16 * 16 + (lane & 3) * 2 + r * 8;
    int n = n8 * 8 + (lane >> 2);
    float w0 = (K     < kdim) ? W[(size_t)K * 128 + n]       : 0.f;
    float w1 = (K + 1 < kdim) ? W[(size_t)(K + 1) * 128 + n] : 0.f;
    __half h0 = __float2half_rn(w0), h1 = __float2half_rn(w1);
    if (lo) {
        h0 = __float2half_rn(w0 - __half2float(h0));
        h1 = __float2half_rn(w1 - __half2float(h1));
    }
    __half2 p = __halves2half2(h0, h1);
    g_Bw[word] = *(uint32_t*)&p;
}

// ---------------- weight chunk loader: 2 k16 (hi 2048 w + lo 2048 w) ----------
__device__ __forceinline__ void load_wc(const uint32_t* __restrict__ gHi,
                                        const uint32_t* __restrict__ gLo,
                                        int c, uint32_t* dst, int tid)
{
    #pragma unroll
    for (int i = 0; i < 2; i++) {
        int v = tid + i * NTT;   // 0..1023 float4 slots
        const uint32_t* src = (v < 512) ? (gHi + c * 2048 + v * 4)
                                        : (gLo + c * 2048 + (v - 512) * 4);
        unsigned sa = (unsigned)__cvta_generic_to_shared(dst + v * 4);
        asm volatile("cp.async.cg.shared.global [%0], [%1], 16;" :: "r"(sa), "l"(src));
    }
}
#define CPC() asm volatile("cp.async.commit_group;")

// ---------------- one GEMM phase: acc += Ah@(Wh+Wl)  (2-pass) --------------
__device__ __forceinline__ void gemm_phase(
    float acc[8][4], const __half* __restrict__ Ah, int astride, int nk16,
    const uint32_t* __restrict__ gHi, const uint32_t* __restrict__ gLo,
    uint32_t* Wbuf, int R0, int t2, int lane, int n8base, int tid)
{
    load_wc(gHi, gLo, 0, Wbuf, tid);        CPC();
    load_wc(gHi, gLo, 1, Wbuf + 4096, tid); CPC();
    int nch = nk16 >> 1;
    for (int c = 0; c < nch; c++) {
        asm volatile("cp.async.wait_group 1;");
        __syncthreads();
        const uint32_t* WB = Wbuf + (c & 1) * 4096;
        #pragma unroll
        for (int kl = 0; kl < 2; kl++) {
            int cb = (c * 2 + kl) * 16 + t2;
            const __half* xh = Ah + R0 * astride + cb;
            uint32_t a0 = *(const uint32_t*)(xh);
            uint32_t a1 = *(const uint32_t*)(xh + 8 * astride);
            uint32_t a2 = *(const uint32_t*)(xh + 8);
            uint32_t a3 = *(const uint32_t*)(xh + 8 * astride + 8);
            const uint32_t* bh = WB + kl * 1024 + lane * 2 + n8base * 64;
            #pragma unroll
            for (int n8 = 0; n8 < 8; n8++) {
                ull b = *(const ull*)(bh + n8 * 64);
                mma16816(acc[n8], a0, a1, a2, a3, (uint32_t)b, (uint32_t)(b >> 32));
            }
            const uint32_t* bl = bh + 2048;
            #pragma unroll
            for (int n8 = 0; n8 < 8; n8++) {
                ull b = *(const ull*)(bl + n8 * 64);
                mma16816(acc[n8], a0, a1, a2, a3, (uint32_t)b, (uint32_t)(b >> 32));
            }
        }
        __syncthreads();
        if (c + 2 < nch) load_wc(gHi, gLo, c + 2, Wbuf + (c & 1) * 4096, tid);
        CPC();
    }
}

// ---------------- LN + ReLU + fp16 store (cross-half smem reduction) --------
__device__ __forceinline__ void ln_store(float acc[8][4],
    const float* __restrict__ gam, const float* __restrict__ bet,
    __half* HH, float* sred, float* qred,
    int R0, int t2, int half_id, int n8base)
{
    float s0 = 0.f, q0 = 0.f, s1 = 0.f, q1 = 0.f;
    #pragma unroll
    for (int n8 = 0; n8 < 8; n8++) {
        s0 += acc[n8][0] + acc[n8][1];
        q0 += acc[n8][0]*acc[n8][0] + acc[n8][1]*acc[n8][1];
        s1 += acc[n8][2] + acc[n8][3];
        q1 += acc[n8][2]*acc[n8][2] + acc[n8][3]*acc[n8][3];
    }
    #pragma unroll
    for (int o = 1; o < 4; o <<= 1) {
        s0 += __shfl_xor_sync(0xffffffffu, s0, o);
        q0 += __shfl_xor_sync(0xffffffffu, q0, o);
        s1 += __shfl_xor_sync(0xffffffffu, s1, o);
        q1 += __shfl_xor_sync(0xffffffffu, q1, o);
    }
    int R1 = R0 + 8;
    sred[R0 * 2 + half_id] = s0; qred[R0 * 2 + half_id] = q0;
    sred[R1 * 2 + half_id] = s1; qred[R1 * 2 + half_id] = q1;
    __syncthreads();
    float S0 = sred[R0*2] + sred[R0*2+1], Q0 = qred[R0*2] + qred[R0*2+1];
    float S1 = sred[R1*2] + sred[R1*2+1], Q1 = qred[R1*2] + qred[R1*2+1];
    float mu0 = S0 * (1.f/128.f), mu1 = S1 * (1.f/128.f);
    float rs0 = rsqrtf(fmaxf(Q0 * (1.f/128.f) - mu0*mu0, 0.f) + 1e-5f);
    float rs1 = rsqrtf(fmaxf(Q1 * (1.f/128.f) - mu1*mu1, 0.f) + 1e-5f);
    #pragma unroll
    for (int n8 = 0; n8 < 8; n8++) {
        int col = (n8base + n8) * 8 + t2;
        float g0 = gam[col], g1 = gam[col+1], b0 = bet[col], b1 = bet[col+1];
        float h00 = fmaxf(g0 * (acc[n8][0] - mu0) * rs0 + b0, 0.f);
        float h01 = fmaxf(g1 * (acc[n8][1] - mu0) * rs0 + b1, 0.f);
        float h10 = fmaxf(g0 * (acc[n8][2] - mu1) * rs1 + b0, 0.f);
        float h11 = fmaxf(g1 * (acc[n8][3] - mu1) * rs1 + b1, 0.f);
        *(uint32_t*)(HH + R0 * 136 + col) = packh2(h00, h01);
        *(uint32_t*)(HH + R1 * 136 + col) = packh2(h10, h11);
    }
}

// ---------------- triplet kernel ----------------
// smem (bytes): XH 0(51200) HH 51200(34816) Wbuf 86016(32768)
// bias 118784(4096) kjS 122880(512) jiS 123392(512)
// sred 123904(1024) qred 124928(1024) = 125952
#define SMEM_T 125952

__global__ void __launch_bounds__(NTT, 1) triplet_mma_kernel(
    const float* __restrict__ h_bond, const float* __restrict__ pos,
    const float* __restrict__ kb1, const float* __restrict__ kg,
    const float* __restrict__ kb,  const float* __restrict__ kb2,
    const float* __restrict__ vb1, const float* __restrict__ vg,
    const float* __restrict__ vb,  const float* __restrict__ vb2,
    const int* __restrict__ idx_i, const int* __restrict__ idx_j,
    const int* __restrict__ idx_k, const int* __restrict__ idx_kj,
    const int* __restrict__ idx_ji, int blk0, int T)
{
    extern __shared__ char smem[];
    __half* XH = (__half*)(smem);
    __half* HH = (__half*)(smem + 51200);
    uint32_t* Wbuf = (uint32_t*)(smem + 86016);
    float* bias = (float*)(smem + 118784);
    int* kjS = (int*)(smem + 122880);
    int* jiS = (int*)(smem + 123392);
    float* sred = (float*)(smem + 123904);
    float* qred = (float*)(smem + 124928);

    int tid = threadIdx.x, lane = tid & 31, w = tid >> 5;
    int g = lane >> 2, t2 = (lane & 3) * 2;
    int R0 = (w & 7) * 16 + g, R1 = R0 + 8;
    int half_id = w >> 3;            // 0: cols 0..63, 1: cols 64..127
    int n8base = half_id * 8;
    int t0 = (blockIdx.x + blk0) * 128;

    // zero XH (51200 B = 3200 uint4)
    for (int v = tid; v < 3200; v += NTT)
        ((uint4*)smem)[v] = make_uint4(0, 0, 0, 0);
    {
        const float* srcs[8] = {kb1, kg, kb, kb2, vb1, vg, vb, vb2};
        for (int v = tid; v < 1024; v += NTT) bias[v] = srcs[v >> 7][v & 127];
    }
    __syncthreads();

    // indices + angular features (cols 168..181)
    if (tid < 128) {
        int t = t0 + tid;
        int kj = -1, ji = -1;
        float vals[14];
        #pragma unroll
        for (int p = 0; p < 14; p++) vals[p] = 0.f;
        if (t < T) {
            kj = idx_kj[t]; ji = idx_ji[t];
            int ii = idx_i[t], jj = idx_j[t], kk = idx_k[t];
            float pix = pos[ii*3+0], piy = pos[ii*3+1], piz = pos[ii*3+2];
            float jx = pos[jj*3+0]-pix, jy = pos[jj*3+1]-piy, jz = pos[jj*3+2]-piz;
            float kx = pos[kk*3+0]-pix, ky = pos[kk*3+1]-piy, kz = pos[kk*3+2]-piz;
            float dt = jx*kx + jy*ky + jz*kz;
            float cx = jy*kz - jz*ky, cy = jz*kx - jx*kz, cz = jx*ky - jy*kx;
            float cr = sqrtf(cx*cx + cy*cy + cz*cz);
            float ang = atan2f(cr, dt);
            vals[0] = ang;
            const float fq[6] = {1.f, 2.f, 3.f, 1.f, 0.5f, 1.f/3.f};
            #pragma unroll
            for (int i = 0; i < 6; i++) {
                vals[1 + i] = sinf(ang * fq[i]);
                vals[7 + i] = cosf(ang * fq[i]);
            }
        }
        kjS[tid] = kj; jiS[tid] = ji;
        #pragma unroll
        for (int p = 0; p < 7; p++)
            *(uint32_t*)(XH + tid * 200 + 168 + 2*p) = packh2(vals[2*p], vals[2*p+1]);
    }
    __syncthreads();

    // h_bond[idx_kj] -> cols 0..127
    for (int v = tid; v < 128 * 32; v += NTT) {
        int row = v >> 5, c4 = v & 31;
        int kj = kjS[row];
        if (kj >= 0) {
            float4 x = ((const float4*)h_bond)[(size_t)kj * 32 + c4];
            *(uint2*)(XH + row * 200 + c4 * 4) =
                make_uint2(packh2(x.x, x.y), packh2(x.z, x.w));
        }
    }
    // rfeat -> cols 128..147 (kj), 148..167 (ji)
    for (int v = tid; v < 128 * 20; v += NTT) {
        int row = v / 20, u = v % 20;
        float f0 = 0.f, f1 = 0.f; int col; bool ok = false;
        if (u < 10) {
            int kj = kjS[row]; col = 128 + 2 * u;
            if (kj >= 0) { f0 = g_rfeat[kj*20 + 2*u]; f1 = g_rfeat[kj*20 + 2*u + 1]; ok = true; }
        } else {
            int j = u - 10, ji = jiS[row]; col = 148 + 2 * j;
            if (ji >= 0) { f0 = g_rfeat[ji*20 + 2*j]; f1 = g_rfeat[ji*20 + 2*j + 1]; ok = true; }
        }
        if (ok)
            *(uint32_t*)(XH + row * 200 + col) = packh2(f0, f1);
    }
    __syncthreads();

    float acc[8][4];

    // ======== k-MLP ========
    #pragma unroll
    for (int n8 = 0; n8 < 8; n8++) {
        acc[n8][0] = bias[0*128 + (n8base + n8)*8 + t2];
        acc[n8][1] = bias[0*128 + (n8base + n8)*8 + t2 + 1];
        acc[n8][2] = acc[n8][0];
        acc[n8][3] = acc[n8][1];
    }
    gemm_phase(acc, XH, 200, 12, g_Bw + 0, g_Bw + 12288, Wbuf, R0, t2, lane, n8base, tid);
    ln_store(acc, bias + 128, bias + 256, HH, sred, qred, R0, t2, half_id, n8base);
    __syncthreads();

    #pragma unroll
    for (int n8 = 0; n8 < 8; n8++) {
        acc[n8][0] = bias[3*128 + (n8base + n8)*8 + t2];
        acc[n8][1] = bias[3*128 + (n8base + n8)*8 + t2 + 1];
        acc[n8][2] = acc[n8][0];
        acc[n8][3] = acc[n8][1];
    }
    gemm_phase(acc, HH, 136, 8, g_Bw + 49152, g_Bw + 57344, Wbuf, R0, t2, lane, n8base, tid);

    // logits epilogue (head = global n8 index; warp-local)
    {
        int ji0 = jiS[R0], ji1 = jiS[R1];
        float lg0[8], lg1[8];
        #pragma unroll
        for (int n8 = 0; n8 < 8; n8++) { lg0[n8] = 0.f; lg1[n8] = 0.f; }
        if (ji0 >= 0) {
            #pragma unroll
            for (int n8 = 0; n8 < 8; n8++) {
                float2 qv = *(const float2*)(g_q + (size_t)ji0 * 128 + (n8base + n8) * 8 + t2);
                lg0[n8] = acc[n8][0] * qv.x + acc[n8][1] * qv.y;
            }
        }
        if (ji1 >= 0) {
            #pragma unroll
            for (int n8 = 0; n8 < 8; n8++) {
                float2 qv = *(const float2*)(g_q + (size_t)ji1 * 128 + (n8base + n8) * 8 + t2);
                lg1[n8] = acc[n8][2] * qv.x + acc[n8][3] * qv.y;
            }
        }
        #pragma unroll
        for (int o = 1; o < 4; o <<= 1)
            #pragma unroll
            for (int n8 = 0; n8 < 8; n8++) {
                lg0[n8] += __shfl_xor_sync(0xffffffffu, lg0[n8], o);
                lg1[n8] += __shfl_xor_sync(0xffffffffu, lg1[n8], o);
            }
        const float sc = 0.3535533905932738f;
        int tq = lane & 3;
        if (ji0 >= 0)
            *(float2*)(g_logits + (size_t)(t0 + R0) * 16 + n8base + 2 * tq) =
                make_float2(lg0[2*tq] * sc, lg0[2*tq+1] * sc);
        if (ji1 >= 0)
            *(float2*)(g_logits + (size_t)(t0 + R1) * 16 + n8base + 2 * tq) =
                make_float2(lg1[2*tq] * sc, lg1[2*tq+1] * sc);
    }

    // ======== v-MLP ========
    #pragma unroll
    for (int n8 = 0; n8 < 8; n8++) {
        acc[n8][0] = bias[4*128 + (n8base + n8)*8 + t2];
        acc[n8][1] = bias[4*128 + (n8base + n8)*8 + t2 + 1];
        acc[n8][2] = acc[n8][0];
        acc[n8][3] = acc[n8][1];
    }
    gemm_phase(acc, XH, 200, 12, g_Bw + 24576, g_Bw + 36864, Wbuf, R0, t2, lane, n8base, tid);
    __syncthreads();
    ln_store(acc, bias + 5*128, bias + 6*128, HH, sred, qred, R0, t2, half_id, n8base);
    __syncthreads();

    #pragma unroll
    for (int n8 = 0; n8 < 8; n8++) {
        acc[n8][0] = bias[7*128 + (n8base + n8)*8 + t2];
        acc[n8][1] = bias[7*128 + (n8base + n8)*8 + t2 + 1];
        acc[n8][2] = acc[n8][0];
        acc[n8][3] = acc[n8][1];
    }
    gemm_phase(acc, HH, 136, 8, g_Bw + 65536, g_Bw + 73728, Wbuf, R0, t2, lane, n8base, tid);

    // V epilogue
    {
        int ji0 = jiS[R0], ji1 = jiS[R1];
        #pragma unroll
        for (int n8 = 0; n8 < 8; n8++) {
            int col = (n8base + n8) * 8 + t2;
            if (ji0 >= 0)
                *(float2*)(g_v + (size_t)(t0 + R0) * 128 + col) =
                    make_float2(acc[n8][0], acc[n8][1]);
            if (ji1 >= 0)
                *(float2*)(g_v + (size_t)(t0 + R1) * 128 + col) =
                    make_float2(acc[n8][2], acc[n8][3]);
        }
    }
}

// ======================= r9 SIMT kernels (q/edge/attn) ==================
__device__ __forceinline__ void load_chunk_nc(const float* __restrict__ W, int kdim,
                                              int c, float* dst, int tid)
{
    #pragma unroll
    for (int i = 0; i < 2; i++) {
        int v = tid + i * NTQ;
        int krow = c * 32 + (v >> 5);
        float* d = dst + v * 4;
        if (krow < kdim) {
            unsigned sa = (unsigned)__cvta_generic_to_shared(d);
            const float* s = W + (size_t)krow * 128 + (v & 31) * 4;
            asm volatile("cp.async.cg.shared.global [%0], [%1], 16;" :: "r"(sa), "l"(s));
        } else { d[0]=0.f; d[1]=0.f; d[2]=0.f; d[3]=0.f; }
    }
}

__device__ __forceinline__ void gemm_chunk(const float* __restrict__ Xl, int xstride,
                                           const float* __restrict__ Wp, int w8, ull acc[4][4])
{
    #pragma unroll
    for (int kq = 0; kq < 8; ++kq) {
        float4 act[4];
        #pragma unroll
        for (int rr = 0; rr < 4; rr++)
            act[rr] = *(const float4*)(Xl + rr * 32 * xstride + kq * 4);
        #pragma unroll
        for (int k4 = 0; k4 < 4; ++k4) {
            const ulonglong2* wp = (const ulonglong2*)(Wp + (kq * 4 + k4) * 128 + w8);
            ulonglong2 wA = wp[0], wB = wp[1];
            #pragma unroll
            for (int rr = 0; rr < 4; rr++) {
                float a = (k4 == 0) ? act[rr].x : (k4 == 1) ? act[rr].y
                        : (k4 == 2) ? act[rr].z : act[rr].w;
                ull ap = pack2(a);
                fma2(acc[rr][0], ap, wA.x); fma2(acc[rr][1], ap, wA.y);
                fma2(acc[rr][2], ap, wB.x); fma2(acc[rr][3], ap, wB.y);
            }
        }
    }
}

__device__ __forceinline__ void ln_relu_q(ull acc[4][4],
    const float* __restrict__ b1, const float* __restrict__ gam, const float* __restrict__ bet,
    float* Hs, float* red, float* mus, float* rss, int tid, int l, int w)
{
    const int w8 = w * 8;
    float a1[4][8];
    #pragma unroll
    for (int r = 0; r < 4; r++) {
        float s = 0.f, s2 = 0.f;
        #pragma unroll
        for (int cp = 0; cp < 4; cp++) {
            float2 t = unpack2(acc[r][cp]);
            float x0 = t.x + b1[w8 + cp*2], x1 = t.y + b1[w8 + cp*2 + 1];
            a1[r][cp*2] = x0; a1[r][cp*2+1] = x1;
            s += x0 + x1; s2 += x0*x0 + x1*x1;
        }
        int row = r * 32 + l;
        red[row*17 + w] = s; red[2176 + row*17 + w] = s2;
    }
    __syncthreads();
    if (tid < 128) {
        float s = 0.f, s2 = 0.f;
        #pragma unroll
        for (int i = 0; i < 16; i++) { s += red[tid*17 + i]; s2 += red[2176 + tid*17 + i]; }
        float mu = s * (1.f/128.f);
        float var = fmaxf(s2 * (1.f/128.f) - mu*mu, 0.f);
        mus[tid] = mu; rss[tid] = rsqrtf(var + 1e-5f);
    }
    __syncthreads();
    #pragma unroll
    for (int r = 0; r < 4; r++) {
        int row = r * 32 + l;
        float mu = mus[row], rs = rss[row];
        float4 hv[2];
        #pragma unroll
        for (int c = 0; c < 8; c++) {
            float h = gam[w8 + c] * (a1[r][c] - mu) * rs + bet[w8 + c];
            ((float*)hv)[c] = fmaxf(h, 0.f);
        }
        float4* hp = (float4*)(Hs + row * 132 + w8);
        hp[0] = hv[0]; hp[1] = hv[1];
    }
}

__global__ void __launch_bounds__(NTQ, 1) q_mlp_kernel(const float* __restrict__ h_bond,
    const float* __restrict__ W1, const float* __restrict__ b1,
    const float* __restrict__ gam, const float* __restrict__ bet,
    const float* __restrict__ W2, const float* __restrict__ b2, int E)
{
    extern __shared__ float sm[];
    float* Xs  = sm;
    float* Hs  = Xs + 128*132;
    float* Wb  = Hs + 128*132;
    float* red = Wb + 2*4096;
    float* mus = red + 2*2176;
    float* rss = mus + 128;
    int tid = threadIdx.x, l = tid & 31, w = tid >> 5;
    const int w8 = w * 8;
    int e0 = blockIdx.x * 128;

    load_chunk_nc(W1, 128, 0, Wb + 0,    tid); CPC();
    load_chunk_nc(W1, 128, 1, Wb + 4096, tid); CPC();

    for (int v = tid; v < 128*32; v += NTQ) {
        int row = v >> 5, c4 = v & 31;
        float4 x = make_float4(0.f, 0.f, 0.f, 0.f);
        if (e0 + row < E) x = ((const float4*)h_bond)[(size_t)(e0 + row)*32 + c4];
        float* xr = Xs + row*132 + c4*4;
        xr[0] = x.x; xr[1] = x.y; xr[2] = x.z; xr[3] = x.w;
    }

    ull a1p[4][4];
    #pragma unroll
    for (int r = 0; r < 4; r++)
        #pragma unroll
        for (int c = 0; c < 4; c++) a1p[r][c] = 0ULL;
    const float* Xl = Xs + l * 132;
    for (int c = 0; c < 4; c++) {
        asm volatile("cp.async.wait_group 1;");
        __syncthreads();
        gemm_chunk(Xl + c*32, 132, Wb + (c & 1)*4096, w8, a1p);
        __syncthreads();
        if (c + 2 < 4) load_chunk_nc(W1, 128, c + 2, Wb + (c & 1)*4096, tid);
        CPC();
    }
    load_chunk_nc(W2, 128, 0, Wb + 0,    tid); CPC();
    load_chunk_nc(W2, 128, 1, Wb + 4096, tid); CPC();

    ln_relu_q(a1p, b1, gam, bet, Hs, red, mus, rss, tid, l, w);

    ull a2p[4][4];
    #pragma unroll
    for (int r = 0; r < 4; r++)
        #pragma unroll
        for (int c = 0; c < 4; c++) a2p[r][c] = 0ULL;
    const float* Hl = Hs + l * 132;
    for (int c = 0; c < 4; c++) {
        asm volatile("cp.async.wait_group 1;");
        __syncthreads();
        gemm_chunk(Hl + c*32, 132, Wb + (c & 1)*4096, w8, a2p);
        __syncthreads();
        if (c + 2 < 4) load_chunk_nc(W2, 128, c + 2, Wb + (c & 1)*4096, tid);
        CPC();
    }
    #pragma unroll
    for (int r = 0; r < 4; r++) {
        int row = r * 32 + l;
        int e = e0 + row;
        if (e < E) {
            float o[8];
            #pragma unroll
            for (int cp = 0; cp < 4; cp++) {
                float2 t = unpack2(a2p[r][cp]);
                o[cp*2] = t.x + b2[w8 + cp*2]; o[cp*2+1] = t.y + b2[w8 + cp*2 + 1];
            }
            float4* qp = (float4*)(g_q + (size_t)e*128 + w8);
            qp[0] = *(float4*)&o[0]; qp[1] = *(float4*)&o[4];
        }
    }
}

__global__ void edge_feat_kernel(const float* __restrict__ pos,
                                 const int* __restrict__ brow,
                                 const int* __restrict__ bcol, int E)
{
    int e = blockIdx.x * blockDim.x + threadIdx.x;
    if (e >= E) return;
    int r = brow[e], c = bcol[e];
    float dx = pos[c*3+0] - pos[r*3+0];
    float dy = pos[c*3+1] - pos[r*3+1];
    float dz = pos[c*3+2] - pos[r*3+2];
    float d  = sqrtf(dx*dx + dy*dy + dz*dz);
    const float step  = 10.0f / 19.0f;
    const float coeff = -0.5f / (step * step);
    #pragma unroll
    for (int g = 0; g < 20; ++g) {
        float t = d - step * (float)g;
        g_rfeat[e*20 + g] = expf(coeff * t * t);
    }
}

__global__ void attn_out_kernel(const int* __restrict__ idx_ji,
                                int T, int E, float* __restrict__ out)
{
    int warp = (blockIdx.x * blockDim.x + threadIdx.x) >> 5;
    int lane = threadIdx.x & 31;
    if (warp >= E) return;
    int e = warp;
    int lo = 0, hi = T;
    while (lo < hi) { int m = (lo + hi) >> 1; if (idx_ji[m] <  e)     lo = m + 1; else hi = m; }
    int s = lo;
    int hi2 = T;
    while (lo < hi2) { int m = (lo + hi2) >> 1; if (idx_ji[m] < e + 1) lo = m + 1; else hi2 = m; }
    int en = lo;
    int head = lane >> 1, half = lane & 1;
    float mx = -INFINITY;
    for (int t = s; t < en; t++) mx = fmaxf(mx, g_logits[(size_t)t*16 + head]);
    float den = 0.f, ax = 0.f, ay = 0.f, az = 0.f, aw = 0.f;
    for (int t = s; t < en; t++) {
        float w = expf(g_logits[(size_t)t*16 + head] - mx);
        den += w;
        float4 v = *(const float4*)(g_v + (size_t)t*128 + head*8 + half*4);
        ax += w*v.x; ay += w*v.y; az += w*v.z; aw += w*v.w;
    }
    float inv = (en > s) ? (1.f / den) : 0.f;
    *(float4*)(out + (size_t)e*128 + head*8 + half*4) =
        make_float4(ax*inv, ay*inv, az*inv, aw*inv);
}

// ---------------- launcher ----------------
extern "C" void kernel_launch(void* const* d_in, const int* in_sizes, int n_in,
                              void* d_out, int out_size)
{
    const float* h_bond = (const float*)d_in[1];
    const float* pos    = (const float*)d_in[2];
    const float* kW1 = (const float*)d_in[3];
    const float* kb1 = (const float*)d_in[4];
    const float* kg  = (const float*)d_in[5];
    const float* kb  = (const float*)d_in[6];
    const float* kW2 = (const float*)d_in[7];
    const float* kb2 = (const float*)d_in[8];
    const float* vW1 = (const float*)d_in[9];
    const float* vb1 = (const float*)d_in[10];
    const float* vg  = (const float*)d_in[11];
    const float* vb  = (const float*)d_in[12];
    const float* vW2 = (const float*)d_in[13];
    const float* vb2 = (const float*)d_in[14];
    const float* qW1 = (const float*)d_in[15];
    const float* qb1 = (const float*)d_in[16];
    const float* qg  = (const float*)d_in[17];
    const float* qb  = (const float*)d_in[18];
    const float* qW2 = (const float*)d_in[19];
    const float* qb2 = (const float*)d_in[20];
    const int* bond_row = (const int*)d_in[21];
    const int* bond_col = (const int*)d_in[22];
    const int* idx_i  = (const int*)d_in[23];
    const int* idx_j  = (const int*)d_in[24];
    const int* idx_k  = (const int*)d_in[25];
    const int* idx_kj = (const int*)d_in[26];
    const int* idx_ji = (const int*)d_in[27];
    int E = in_sizes[21];
    int T = in_sizes[23];

    const int SMEM_Q = (128*132 + 128*132 + 2*4096 + 2*2176 + 256) * 4;
    cudaFuncSetAttribute(q_mlp_kernel,       cudaFuncAttributeMaxDynamicSharedMemorySize, SMEM_Q);
    cudaFuncSetAttribute(triplet_mma_kernel, cudaFuncAttributeMaxDynamicSharedMemorySize, SMEM_T);

    int nb  = (T + 127) / 128;
    int nbA = nb / 2; if (nbA < 1) nbA = 1;
    int nbB = nb - nbA;

    prep_weights<<<80, 1024>>>(kW1, vW1, kW2, vW2);
    edge_feat_kernel<<<(E + 255) / 256, 256>>>(pos, bond_row, bond_col, E);
    q_mlp_kernel<<<(E + 127) / 128, NTQ, SMEM_Q>>>(h_bond, qW1, qb1, qg, qb, qW2, qb2, E);
    triplet_mma_kernel<<<nbA, NTT, SMEM_T>>>(
        h_bond, pos, kb1, kg, kb, kb2, vb1, vg, vb, vb2,
        idx_i, idx_j, idx_k, idx_kj, idx_ji, 0, T);
    if (nbB > 0)
        triplet_mma_kernel<<<nbB, NTT, SMEM_T>>>(
            h_bond, pos, kb1, kg, kb, kb2, vb1, vg, vb, vb2,
            idx_i, idx_j, idx_k, idx_kj, idx_ji, nbA, T);
    attn_out_kernel<<<(E * 32 + 255) / 256, 256>>>(idx_ji, T, E, (float*)d_out);
}

// round 15
// speedup vs baseline: 2.1497x; 1.0443x over previous
#include <cuda_runtime.h>
#include <cuda_fp16.h>
#include <math.h>
#include <stdint.h>

// ---------------------------------------------------------------------------
// BondUpdateLayer, round 15: HMMA m16n8k16 triplet MLPs (2-pass fp16-split),
// warp = 32 rows x 32 cols (B fragments amortized over 2 m-tiles -> 33% fewer
// L1 wavefronts), V stored fp16 (halved attn DRAM traffic).
// ---------------------------------------------------------------------------

#define EN    80000
#define TMAXN 640000
#define NTQ   512
#define NTT   512

typedef unsigned long long ull;

__device__ float  g_rfeat [EN * 20];
__device__ float  g_q     [EN * 128];
__device__ float  g_logits[(size_t)TMAXN * 16];
__device__ __half g_vh    [(size_t)TMAXN * 128];
// fragment-packed weight words (half2 per word):
// kW1h@0, kW1l@12288, vW1h@24576, vW1l@36864 (12288 words each: 12 k16)
// kW2h@49152, kW2l@57344, vW2h@65536, vW2l@73728 (8192 words each: 8 k16)
__device__ __align__(16) uint32_t g_Bw[81920];

// ---------------- helpers ----------------
__device__ __forceinline__ ull pack2(float v) {
    ull r; asm("mov.b64 %0, {%1, %1};" : "=l"(r) : "f"(v)); return r;
}
__device__ __forceinline__ void fma2(ull& d, ull a, ull b) {
    asm("fma.rn.f32x2 %0, %1, %2, %0;" : "+l"(d) : "l"(a), "l"(b));
}
__device__ __forceinline__ float2 unpack2(ull v) {
    float lo, hi; asm("mov.b64 {%0, %1}, %2;" : "=f"(lo), "=f"(hi) : "l"(v));
    return make_float2(lo, hi);
}
__device__ __forceinline__ uint32_t packh2(float f0, float f1) {
    __half2 H = __floats2half2_rn(f0, f1);
    return *(uint32_t*)&H;
}
__device__ __forceinline__ void mma16816(float c[4], uint32_t a0, uint32_t a1,
                                         uint32_t a2, uint32_t a3,
                                         uint32_t b0, uint32_t b1) {
    asm volatile(
        "mma.sync.aligned.m16n8k16.row.col.f32.f16.f16.f32 "
        "{%0,%1,%2,%3},{%4,%5,%6,%7},{%8,%9},{%0,%1,%2,%3};"
        : "+f"(c[0]), "+f"(c[1]), "+f"(c[2]), "+f"(c[3])
        : "r"(a0), "r"(a1), "r"(a2), "r"(a3), "r"(b0), "r"(b1));
}

// ---------------- weight prep: pack into fragment order ----------------
__global__ void prep_weights(const float* __restrict__ kW1, const float* __restrict__ vW1,
                             const float* __restrict__ kW2, const float* __restrict__ vW2)
{
    int word = blockIdx.x * 1024 + threadIdx.x;
    const float* W; int kdim, rem; bool lo;
    if (word < 49152) {
        int img = word / 12288; rem = word % 12288;
        W = (img < 2) ? kW1 : vW1; lo = img & 1; kdim = 181;
    } else {
        int w2 = word - 49152;
        int img = w2 / 8192; rem = w2 % 8192;
        W = (img < 2) ? kW2 : vW2; lo = img & 1; kdim = 128;
    }
    int r = rem & 1, lane = (rem >> 1) & 31, n8 = (rem >> 6) & 15, k16 = rem >> 10;
    int K = k16 * 16 + (lane & 3) * 2 + r * 8;
    int n = n8 * 8 + (lane >> 2);
    float w0 = (K     < kdim) ? W[(size_t)K * 128 + n]       : 0.f;
    float w1 = (K + 1 < kdim) ? W[(size_t)(K + 1) * 128 + n] : 0.f;
    __half h0 = __float2half_rn(w0), h1 = __float2half_rn(w1);
    if (lo) {
        h0 = __float2half_rn(w0 - __half2float(h0));
        h1 = __float2half_rn(w1 - __half2float(h1));
    }
    __half2 p = __halves2half2(h0, h1);
    g_Bw[word] = *(uint32_t*)&p;
}

// ---------------- weight chunk loader: 2 k16 (hi 2048 w + lo 2048 w) ----------
__device__ __forceinline__ void load_wc(const uint32_t* __restrict__ gHi,
                                        const uint32_t* __restrict__ gLo,
                                        int c, uint32_t* dst, int tid)
{
    #pragma unroll
    for (int i = 0; i < 2; i++) {
        int v = tid + i * NTT;   // 0..1023 float4 slots
        const uint32_t* src = (v < 512) ? (gHi + c * 2048 + v * 4)
                                        : (gLo + c * 2048 + (v - 512) * 4);
        unsigned sa = (unsigned)__cvta_generic_to_shared(dst + v * 4);
        asm volatile("cp.async.cg.shared.global [%0], [%1], 16;" :: "r"(sa), "l"(src));
    }
}
#define CPC() asm volatile("cp.async.commit_group;")

// ---------------- one GEMM phase: acc += Ah@(Wh+Wl)  (2-pass) --------------
// warp: 2 m16 tiles (rows R0, R0+16) x 4 n8 blocks (cols n8base*8..+32)
__device__ __forceinline__ void gemm_phase(
    float acc[2][4][4], const __half* __restrict__ Ah, int astride, int nk16,
    const uint32_t* __restrict__ gHi, const uint32_t* __restrict__ gLo,
    uint32_t* Wbuf, int R0, int t2, int lane, int n8base, int tid)
{
    load_wc(gHi, gLo, 0, Wbuf, tid);        CPC();
    load_wc(gHi, gLo, 1, Wbuf + 4096, tid); CPC();
    int nch = nk16 >> 1;
    for (int c = 0; c < nch; c++) {
        asm volatile("cp.async.wait_group 1;");
        __syncthreads();
        const uint32_t* WB = Wbuf + (c & 1) * 4096;
        #pragma unroll
        for (int kl = 0; kl < 2; kl++) {
            int cb = (c * 2 + kl) * 16 + t2;
            uint32_t a[2][4];
            #pragma unroll
            for (int t = 0; t < 2; t++) {
                const __half* xh = Ah + (R0 + t * 16) * astride + cb;
                a[t][0] = *(const uint32_t*)(xh);
                a[t][1] = *(const uint32_t*)(xh + 8 * astride);
                a[t][2] = *(const uint32_t*)(xh + 8);
                a[t][3] = *(const uint32_t*)(xh + 8 * astride + 8);
            }
            const uint32_t* bh = WB + kl * 1024 + lane * 2 + n8base * 64;
            #pragma unroll
            for (int n8 = 0; n8 < 4; n8++) {
                ull b = *(const ull*)(bh + n8 * 64);
                mma16816(acc[0][n8], a[0][0], a[0][1], a[0][2], a[0][3],
                         (uint32_t)b, (uint32_t)(b >> 32));
                mma16816(acc[1][n8], a[1][0], a[1][1], a[1][2], a[1][3],
                         (uint32_t)b, (uint32_t)(b >> 32));
            }
            const uint32_t* bl = bh + 2048;
            #pragma unroll
            for (int n8 = 0; n8 < 4; n8++) {
                ull b = *(const ull*)(bl + n8 * 64);
                mma16816(acc[0][n8], a[0][0], a[0][1], a[0][2], a[0][3],
                         (uint32_t)b, (uint32_t)(b >> 32));
                mma16816(acc[1][n8], a[1][0], a[1][1], a[1][2], a[1][3],
                         (uint32_t)b, (uint32_t)(b >> 32));
            }
        }
        __syncthreads();
        if (c + 2 < nch) load_wc(gHi, gLo, c + 2, Wbuf + (c & 1) * 4096, tid);
        CPC();
    }
}

// ---------------- LN + ReLU + fp16 store (4-way cross-group reduction) -------
__device__ __forceinline__ void ln_store(float acc[2][4][4],
    const float* __restrict__ gam, const float* __restrict__ bet,
    __half* HH, float* sred, float* qred,
    int R0, int t2, int lane, int col_grp, int n8base)
{
    // rows: r(0)=R0, r(1)=R0+8, r(2)=R0+16, r(3)=R0+24
    float s[4], q[4];
    #pragma unroll
    for (int t = 0; t < 2; t++) {
        float sa = 0.f, qa = 0.f, sb = 0.f, qb = 0.f;
        #pragma unroll
        for (int n8 = 0; n8 < 4; n8++) {
            sa += acc[t][n8][0] + acc[t][n8][1];
            qa += acc[t][n8][0]*acc[t][n8][0] + acc[t][n8][1]*acc[t][n8][1];
            sb += acc[t][n8][2] + acc[t][n8][3];
            qb += acc[t][n8][2]*acc[t][n8][2] + acc[t][n8][3]*acc[t][n8][3];
        }
        s[2*t] = sa; q[2*t] = qa; s[2*t+1] = sb; q[2*t+1] = qb;
    }
    #pragma unroll
    for (int o = 1; o < 4; o <<= 1)
        #pragma unroll
        for (int r = 0; r < 4; r++) {
            s[r] += __shfl_xor_sync(0xffffffffu, s[r], o);
            q[r] += __shfl_xor_sync(0xffffffffu, q[r], o);
        }
    if ((lane & 3) == 0) {
        #pragma unroll
        for (int r = 0; r < 4; r++) {
            int row = R0 + r * 8;
            sred[row * 4 + col_grp] = s[r];
            qred[row * 4 + col_grp] = q[r];
        }
    }
    __syncthreads();
    float mu[4], rs[4];
    #pragma unroll
    for (int r = 0; r < 4; r++) {
        int row = R0 + r * 8;
        float S = sred[row*4] + sred[row*4+1] + sred[row*4+2] + sred[row*4+3];
        float Q = qred[row*4] + qred[row*4+1] + qred[row*4+2] + qred[row*4+3];
        mu[r] = S * (1.f/128.f);
        rs[r] = rsqrtf(fmaxf(Q * (1.f/128.f) - mu[r]*mu[r], 0.f) + 1e-5f);
    }
    #pragma unroll
    for (int t = 0; t < 2; t++)
        #pragma unroll
        for (int n8 = 0; n8 < 4; n8++) {
            int col = (n8base + n8) * 8 + t2;
            float g0 = gam[col], g1 = gam[col+1], b0 = bet[col], b1 = bet[col+1];
            int ra = 2*t, rb = 2*t + 1;
            float h00 = fmaxf(g0 * (acc[t][n8][0] - mu[ra]) * rs[ra] + b0, 0.f);
            float h01 = fmaxf(g1 * (acc[t][n8][1] - mu[ra]) * rs[ra] + b1, 0.f);
            float h10 = fmaxf(g0 * (acc[t][n8][2] - mu[rb]) * rs[rb] + b0, 0.f);
            float h11 = fmaxf(g1 * (acc[t][n8][3] - mu[rb]) * rs[rb] + b1, 0.f);
            *(uint32_t*)(HH + (R0 + t*16)     * 136 + col) = packh2(h00, h01);
            *(uint32_t*)(HH + (R0 + t*16 + 8) * 136 + col) = packh2(h10, h11);
        }
}

// ---------------- triplet kernel ----------------
// smem (bytes): XH 0(51200) HH 51200(34816) Wbuf 86016(32768)
// bias 118784(4096) kjS 122880(512) jiS 123392(512)
// sred 123904(2048) qred 125952(2048) = 128000
#define SMEM_T 128000

__global__ void __launch_bounds__(NTT, 1) triplet_mma_kernel(
    const float* __restrict__ h_bond, const float* __restrict__ pos,
    const float* __restrict__ kb1, const float* __restrict__ kg,
    const float* __restrict__ kb,  const float* __restrict__ kb2,
    const float* __restrict__ vb1, const float* __restrict__ vg,
    const float* __restrict__ vb,  const float* __restrict__ vb2,
    const int* __restrict__ idx_i, const int* __restrict__ idx_j,
    const int* __restrict__ idx_k, const int* __restrict__ idx_kj,
    const int* __restrict__ idx_ji, int blk0, int T)
{
    extern __shared__ char smem[];
    __half* XH = (__half*)(smem);
    __half* HH = (__half*)(smem + 51200);
    uint32_t* Wbuf = (uint32_t*)(smem + 86016);
    float* bias = (float*)(smem + 118784);
    int* kjS = (int*)(smem + 122880);
    int* jiS = (int*)(smem + 123392);
    float* sred = (float*)(smem + 123904);
    float* qred = (float*)(smem + 125952);

    int tid = threadIdx.x, lane = tid & 31, w = tid >> 5;
    int g = lane >> 2, t2 = (lane & 3) * 2;
    int row_grp = w & 3, col_grp = w >> 2;  // 4 x 4 warps
    int R0 = row_grp * 32 + g;              // rows R0, R0+8, R0+16, R0+24
    int n8base = col_grp * 4;               // cols [n8base*8, n8base*8+32)
    int t0 = (blockIdx.x + blk0) * 128;

    // zero XH (51200 B = 3200 uint4)
    for (int v = tid; v < 3200; v += NTT)
        ((uint4*)smem)[v] = make_uint4(0, 0, 0, 0);
    {
        const float* srcs[8] = {kb1, kg, kb, kb2, vb1, vg, vb, vb2};
        for (int v = tid; v < 1024; v += NTT) bias[v] = srcs[v >> 7][v & 127];
    }
    __syncthreads();

    // indices + angular features (cols 168..181)
    if (tid < 128) {
        int t = t0 + tid;
        int kj = -1, ji = -1;
        float vals[14];
        #pragma unroll
        for (int p = 0; p < 14; p++) vals[p] = 0.f;
        if (t < T) {
            kj = idx_kj[t]; ji = idx_ji[t];
            int ii = idx_i[t], jj = idx_j[t], kk = idx_k[t];
            float pix = pos[ii*3+0], piy = pos[ii*3+1], piz = pos[ii*3+2];
            float jx = pos[jj*3+0]-pix, jy = pos[jj*3+1]-piy, jz = pos[jj*3+2]-piz;
            float kx = pos[kk*3+0]-pix, ky = pos[kk*3+1]-piy, kz = pos[kk*3+2]-piz;
            float dt = jx*kx + jy*ky + jz*kz;
            float cx = jy*kz - jz*ky, cy = jz*kx - jx*kz, cz = jx*ky - jy*kx;
            float cr = sqrtf(cx*cx + cy*cy + cz*cz);
            float ang = atan2f(cr, dt);
            vals[0] = ang;
            const float fq[6] = {1.f, 2.f, 3.f, 1.f, 0.5f, 1.f/3.f};
            #pragma unroll
            for (int i = 0; i < 6; i++) {
                vals[1 + i] = sinf(ang * fq[i]);
                vals[7 + i] = cosf(ang * fq[i]);
            }
        }
        kjS[tid] = kj; jiS[tid] = ji;
        #pragma unroll
        for (int p = 0; p < 7; p++)
            *(uint32_t*)(XH + tid * 200 + 168 + 2*p) = packh2(vals[2*p], vals[2*p+1]);
    }
    __syncthreads();

    // h_bond[idx_kj] -> cols 0..127
    for (int v = tid; v < 128 * 32; v += NTT) {
        int row = v >> 5, c4 = v & 31;
        int kj = kjS[row];
        if (kj >= 0) {
            float4 x = ((const float4*)h_bond)[(size_t)kj * 32 + c4];
            *(uint2*)(XH + row * 200 + c4 * 4) =
                make_uint2(packh2(x.x, x.y), packh2(x.z, x.w));
        }
    }
    // rfeat -> cols 128..147 (kj), 148..167 (ji)
    for (int v = tid; v < 128 * 20; v += NTT) {
        int row = v / 20, u = v % 20;
        float f0 = 0.f, f1 = 0.f; int col; bool ok = false;
        if (u < 10) {
            int kj = kjS[row]; col = 128 + 2 * u;
            if (kj >= 0) { f0 = g_rfeat[kj*20 + 2*u]; f1 = g_rfeat[kj*20 + 2*u + 1]; ok = true; }
        } else {
            int j = u - 10, ji = jiS[row]; col = 148 + 2 * j;
            if (ji >= 0) { f0 = g_rfeat[ji*20 + 2*j]; f1 = g_rfeat[ji*20 + 2*j + 1]; ok = true; }
        }
        if (ok)
            *(uint32_t*)(XH + row * 200 + col) = packh2(f0, f1);
    }
    __syncthreads();

    float acc[2][4][4];

    // ======== k-MLP ========
    #pragma unroll
    for (int t = 0; t < 2; t++)
        #pragma unroll
        for (int n8 = 0; n8 < 4; n8++) {
            acc[t][n8][0] = bias[0*128 + (n8base + n8)*8 + t2];
            acc[t][n8][1] = bias[0*128 + (n8base + n8)*8 + t2 + 1];
            acc[t][n8][2] = acc[t][n8][0];
            acc[t][n8][3] = acc[t][n8][1];
        }
    gemm_phase(acc, XH, 200, 12, g_Bw + 0, g_Bw + 12288, Wbuf, R0, t2, lane, n8base, tid);
    ln_store(acc, bias + 128, bias + 256, HH, sred, qred, R0, t2, lane, col_grp, n8base);
    __syncthreads();

    #pragma unroll
    for (int t = 0; t < 2; t++)
        #pragma unroll
        for (int n8 = 0; n8 < 4; n8++) {
            acc[t][n8][0] = bias[3*128 + (n8base + n8)*8 + t2];
            acc[t][n8][1] = bias[3*128 + (n8base + n8)*8 + t2 + 1];
            acc[t][n8][2] = acc[t][n8][0];
            acc[t][n8][3] = acc[t][n8][1];
        }
    gemm_phase(acc, HH, 136, 8, g_Bw + 49152, g_Bw + 57344, Wbuf, R0, t2, lane, n8base, tid);

    // logits epilogue: rows R0+{0,8,16,24}, heads n8base..n8base+3
    {
        float lg[4][4];
        #pragma unroll
        for (int r = 0; r < 4; r++)
            #pragma unroll
            for (int n8 = 0; n8 < 4; n8++) lg[r][n8] = 0.f;
        #pragma unroll
        for (int r = 0; r < 4; r++) {
            int row = R0 + r * 8;
            int ji = jiS[row];
            if (ji >= 0) {
                int t = r >> 1, lohi = (r & 1) * 2;
                #pragma unroll
                for (int n8 = 0; n8 < 4; n8++) {
                    float2 qv = *(const float2*)(g_q + (size_t)ji * 128 + (n8base + n8) * 8 + t2);
                    lg[r][n8] = acc[t][n8][lohi] * qv.x + acc[t][n8][lohi + 1] * qv.y;
                }
            }
        }
        #pragma unroll
        for (int o = 1; o < 4; o <<= 1)
            #pragma unroll
            for (int r = 0; r < 4; r++)
                #pragma unroll
                for (int n8 = 0; n8 < 4; n8++)
                    lg[r][n8] += __shfl_xor_sync(0xffffffffu, lg[r][n8], o);
        const float sc = 0.3535533905932738f;
        int tq = lane & 3;
        #pragma unroll
        for (int r = 0; r < 4; r++) {
            int row = R0 + r * 8;
            if (jiS[row] >= 0)
                g_logits[(size_t)(t0 + row) * 16 + n8base + tq] = lg[r][tq] * sc;
        }
    }

    // ======== v-MLP ========
    #pragma unroll
    for (int t = 0; t < 2; t++)
        #pragma unroll
        for (int n8 = 0; n8 < 4; n8++) {
            acc[t][n8][0] = bias[4*128 + (n8base + n8)*8 + t2];
            acc[t][n8][1] = bias[4*128 + (n8base + n8)*8 + t2 + 1];
            acc[t][n8][2] = acc[t][n8][0];
            acc[t][n8][3] = acc[t][n8][1];
        }
    gemm_phase(acc, XH, 200, 12, g_Bw + 24576, g_Bw + 36864, Wbuf, R0, t2, lane, n8base, tid);
    __syncthreads();
    ln_store(acc, bias + 5*128, bias + 6*128, HH, sred, qred, R0, t2, lane, col_grp, n8base);
    __syncthreads();

    #pragma unroll
    for (int t = 0; t < 2; t++)
        #pragma unroll
        for (int n8 = 0; n8 < 4; n8++) {
            acc[t][n8][0] = bias[7*128 + (n8base + n8)*8 + t2];
            acc[t][n8][1] = bias[7*128 + (n8base + n8)*8 + t2 + 1];
            acc[t][n8][2] = acc[t][n8][0];
            acc[t][n8][3] = acc[t][n8][1];
        }
    gemm_phase(acc, HH, 136, 8, g_Bw + 65536, g_Bw + 73728, Wbuf, R0, t2, lane, n8base, tid);

    // V epilogue (fp16 store)
    #pragma unroll
    for (int t = 0; t < 2; t++) {
        int rA = R0 + t * 16, rB = rA + 8;
        int jiA = jiS[rA], jiB = jiS[rB];
        #pragma unroll
        for (int n8 = 0; n8 < 4; n8++) {
            int col = (n8base + n8) * 8 + t2;
            if (jiA >= 0)
                *(uint32_t*)(g_vh + (size_t)(t0 + rA) * 128 + col) =
                    packh2(acc[t][n8][0], acc[t][n8][1]);
            if (jiB >= 0)
                *(uint32_t*)(g_vh + (size_t)(t0 + rB) * 128 + col) =
                    packh2(acc[t][n8][2], acc[t][n8][3]);
        }
    }
}

// ======================= r9 SIMT kernels (q/edge/attn) ==================
__device__ __forceinline__ void load_chunk_nc(const float* __restrict__ W, int kdim,
                                              int c, float* dst, int tid)
{
    #pragma unroll
    for (int i = 0; i < 2; i++) {
        int v = tid + i * NTQ;
        int krow = c * 32 + (v >> 5);
        float* d = dst + v * 4;
        if (krow < kdim) {
            unsigned sa = (unsigned)__cvta_generic_to_shared(d);
            const float* s = W + (size_t)krow * 128 + (v & 31) * 4;
            asm volatile("cp.async.cg.shared.global [%0], [%1], 16;" :: "r"(sa), "l"(s));
        } else { d[0]=0.f; d[1]=0.f; d[2]=0.f; d[3]=0.f; }
    }
}

__device__ __forceinline__ void gemm_chunk(const float* __restrict__ Xl, int xstride,
                                           const float* __restrict__ Wp, int w8, ull acc[4][4])
{
    #pragma unroll
    for (int kq = 0; kq < 8; ++kq) {
        float4 act[4];
        #pragma unroll
        for (int rr = 0; rr < 4; rr++)
            act[rr] = *(const float4*)(Xl + rr * 32 * xstride + kq * 4);
        #pragma unroll
        for (int k4 = 0; k4 < 4; ++k4) {
            const ulonglong2* wp = (const ulonglong2*)(Wp + (kq * 4 + k4) * 128 + w8);
            ulonglong2 wA = wp[0], wB = wp[1];
            #pragma unroll
            for (int rr = 0; rr < 4; rr++) {
                float a = (k4 == 0) ? act[rr].x : (k4 == 1) ? act[rr].y
                        : (k4 == 2) ? act[rr].z : act[rr].w;
                ull ap = pack2(a);
                fma2(acc[rr][0], ap, wA.x); fma2(acc[rr][1], ap, wA.y);
                fma2(acc[rr][2], ap, wB.x); fma2(acc[rr][3], ap, wB.y);
            }
        }
    }
}

__device__ __forceinline__ void ln_relu_q(ull acc[4][4],
    const float* __restrict__ b1, const float* __restrict__ gam, const float* __restrict__ bet,
    float* Hs, float* red, float* mus, float* rss, int tid, int l, int w)
{
    const int w8 = w * 8;
    float a1[4][8];
    #pragma unroll
    for (int r = 0; r < 4; r++) {
        float s = 0.f, s2 = 0.f;
        #pragma unroll
        for (int cp = 0; cp < 4; cp++) {
            float2 t = unpack2(acc[r][cp]);
            float x0 = t.x + b1[w8 + cp*2], x1 = t.y + b1[w8 + cp*2 + 1];
            a1[r][cp*2] = x0; a1[r][cp*2+1] = x1;
            s += x0 + x1; s2 += x0*x0 + x1*x1;
        }
        int row = r * 32 + l;
        red[row*17 + w] = s; red[2176 + row*17 + w] = s2;
    }
    __syncthreads();
    if (tid < 128) {
        float s = 0.f, s2 = 0.f;
        #pragma unroll
        for (int i = 0; i < 16; i++) { s += red[tid*17 + i]; s2 += red[2176 + tid*17 + i]; }
        float mu = s * (1.f/128.f);
        float var = fmaxf(s2 * (1.f/128.f) - mu*mu, 0.f);
        mus[tid] = mu; rss[tid] = rsqrtf(var + 1e-5f);
    }
    __syncthreads();
    #pragma unroll
    for (int r = 0; r < 4; r++) {
        int row = r * 32 + l;
        float mu = mus[row], rs = rss[row];
        float4 hv[2];
        #pragma unroll
        for (int c = 0; c < 8; c++) {
            float h = gam[w8 + c] * (a1[r][c] - mu) * rs + bet[w8 + c];
            ((float*)hv)[c] = fmaxf(h, 0.f);
        }
        float4* hp = (float4*)(Hs + row * 132 + w8);
        hp[0] = hv[0]; hp[1] = hv[1];
    }
}

__global__ void __launch_bounds__(NTQ, 1) q_mlp_kernel(const float* __restrict__ h_bond,
    const float* __restrict__ W1, const float* __restrict__ b1,
    const float* __restrict__ gam, const float* __restrict__ bet,
    const float* __restrict__ W2, const float* __restrict__ b2, int E)
{
    extern __shared__ float sm[];
    float* Xs  = sm;
    float* Hs  = Xs + 128*132;
    float* Wb  = Hs + 128*132;
    float* red = Wb + 2*4096;
    float* mus = red + 2*2176;
    float* rss = mus + 128;
    int tid = threadIdx.x, l = tid & 31, w = tid >> 5;
    const int w8 = w * 8;
    int e0 = blockIdx.x * 128;

    load_chunk_nc(W1, 128, 0, Wb + 0,    tid); CPC();
    load_chunk_nc(W1, 128, 1, Wb + 4096, tid); CPC();

    for (int v = tid; v < 128*32; v += NTQ) {
        int row = v >> 5, c4 = v & 31;
        float4 x = make_float4(0.f, 0.f, 0.f, 0.f);
        if (e0 + row < E) x = ((const float4*)h_bond)[(size_t)(e0 + row)*32 + c4];
        float* xr = Xs + row*132 + c4*4;
        xr[0] = x.x; xr[1] = x.y; xr[2] = x.z; xr[3] = x.w;
    }

    ull a1p[4][4];
    #pragma unroll
    for (int r = 0; r < 4; r++)
        #pragma unroll
        for (int c = 0; c < 4; c++) a1p[r][c] = 0ULL;
    const float* Xl = Xs + l * 132;
    for (int c = 0; c < 4; c++) {
        asm volatile("cp.async.wait_group 1;");
        __syncthreads();
        gemm_chunk(Xl + c*32, 132, Wb + (c & 1)*4096, w8, a1p);
        __syncthreads();
        if (c + 2 < 4) load_chunk_nc(W1, 128, c + 2, Wb + (c & 1)*4096, tid);
        CPC();
    }
    load_chunk_nc(W2, 128, 0, Wb + 0,    tid); CPC();
    load_chunk_nc(W2, 128, 1, Wb + 4096, tid); CPC();

    ln_relu_q(a1p, b1, gam, bet, Hs, red, mus, rss, tid, l, w);

    ull a2p[4][4];
    #pragma unroll
    for (int r = 0; r < 4; r++)
        #pragma unroll
        for (int c = 0; c < 4; c++) a2p[r][c] = 0ULL;
    const float* Hl = Hs + l * 132;
    for (int c = 0; c < 4; c++) {
        asm volatile("cp.async.wait_group 1;");
        __syncthreads();
        gemm_chunk(Hl + c*32, 132, Wb + (c & 1)*4096, w8, a2p);
        __syncthreads();
        if (c + 2 < 4) load_chunk_nc(W2, 128, c + 2, Wb + (c & 1)*4096, tid);
        CPC();
    }
    #pragma unroll
    for (int r = 0; r < 4; r++) {
        int row = r * 32 + l;
        int e = e0 + row;
        if (e < E) {
            float o[8];
            #pragma unroll
            for (int cp = 0; cp < 4; cp++) {
                float2 t = unpack2(a2p[r][cp]);
                o[cp*2] = t.x + b2[w8 + cp*2]; o[cp*2+1] = t.y + b2[w8 + cp*2 + 1];
            }
            float4* qp = (float4*)(g_q + (size_t)e*128 + w8);
            qp[0] = *(float4*)&o[0]; qp[1] = *(float4*)&o[4];
        }
    }
}

__global__ void edge_feat_kernel(const float* __restrict__ pos,
                                 const int* __restrict__ brow,
                                 const int* __restrict__ bcol, int E)
{
    int e = blockIdx.x * blockDim.x + threadIdx.x;
    if (e >= E) return;
    int r = brow[e], c = bcol[e];
    float dx = pos[c*3+0] - pos[r*3+0];
    float dy = pos[c*3+1] - pos[r*3+1];
    float dz = pos[c*3+2] - pos[r*3+2];
    float d  = sqrtf(dx*dx + dy*dy + dz*dz);
    const float step  = 10.0f / 19.0f;
    const float coeff = -0.5f / (step * step);
    #pragma unroll
    for (int g = 0; g < 20; ++g) {
        float t = d - step * (float)g;
        g_rfeat[e*20 + g] = expf(coeff * t * t);
    }
}

__global__ void attn_out_kernel(const int* __restrict__ idx_ji,
                                int T, int E, float* __restrict__ out)
{
    int warp = (blockIdx.x * blockDim.x + threadIdx.x) >> 5;
    int lane = threadIdx.x & 31;
    if (warp >= E) return;
    int e = warp;
    int lo = 0, hi = T;
    while (lo < hi) { int m = (lo + hi) >> 1; if (idx_ji[m] <  e)     lo = m + 1; else hi = m; }
    int s = lo;
    int hi2 = T;
    while (lo < hi2) { int m = (lo + hi2) >> 1; if (idx_ji[m] < e + 1) lo = m + 1; else hi2 = m; }
    int en = lo;
    int head = lane >> 1, half = lane & 1;
    float mx = -INFINITY;
    for (int t = s; t < en; t++) mx = fmaxf(mx, g_logits[(size_t)t*16 + head]);
    float den = 0.f, ax = 0.f, ay = 0.f, az = 0.f, aw = 0.f;
    for (int t = s; t < en; t++) {
        float w = expf(g_logits[(size_t)t*16 + head] - mx);
        den += w;
        uint2 raw = *(const uint2*)(g_vh + (size_t)t*128 + head*8 + half*4);
        float2 v0 = __half22float2(*(const __half2*)&raw.x);
        float2 v1 = __half22float2(*(const __half2*)&raw.y);
        ax += w*v0.x; ay += w*v0.y; az += w*v1.x; aw += w*v1.y;
    }
    float inv = (en > s) ? (1.f / den) : 0.f;
    *(float4*)(out + (size_t)e*128 + head*8 + half*4) =
        make_float4(ax*inv, ay*inv, az*inv, aw*inv);
}

// ---------------- launcher ----------------
extern "C" void kernel_launch(void* const* d_in, const int* in_sizes, int n_in,
                              void* d_out, int out_size)
{
    const float* h_bond = (const float*)d_in[1];
    const float* pos    = (const float*)d_in[2];
    const float* kW1 = (const float*)d_in[3];
    const float* kb1 = (const float*)d_in[4];
    const float* kg  = (const float*)d_in[5];
    const float* kb  = (const float*)d_in[6];
    const float* kW2 = (const float*)d_in[7];
    const float* kb2 = (const float*)d_in[8];
    const float* vW1 = (const float*)d_in[9];
    const float* vb1 = (const float*)d_in[10];
    const float* vg  = (const float*)d_in[11];
    const float* vb  = (const float*)d_in[12];
    const float* vW2 = (const float*)d_in[13];
    const float* vb2 = (const float*)d_in[14];
    const float* qW1 = (const float*)d_in[15];
    const float* qb1 = (const float*)d_in[16];
    const float* qg  = (const float*)d_in[17];
    const float* qb  = (const float*)d_in[18];
    const float* qW2 = (const float*)d_in[19];
    const float* qb2 = (const float*)d_in[20];
    const int* bond_row = (const int*)d_in[21];
    const int* bond_col = (const int*)d_in[22];
    const int* idx_i  = (const int*)d_in[23];
    const int* idx_j  = (const int*)d_in[24];
    const int* idx_k  = (const int*)d_in[25];
    const int* idx_kj = (const int*)d_in[26];
    const int* idx_ji = (const int*)d_in[27];
    int E = in_sizes[21];
    int T = in_sizes[23];

    const int SMEM_Q = (128*132 + 128*132 + 2*4096 + 2*2176 + 256) * 4;
    cudaFuncSetAttribute(q_mlp_kernel,       cudaFuncAttributeMaxDynamicSharedMemorySize, SMEM_Q);
    cudaFuncSetAttribute(triplet_mma_kernel, cudaFuncAttributeMaxDynamicSharedMemorySize, SMEM_T);

    int nb  = (T + 127) / 128;
    int nbA = nb / 2; if (nbA < 1) nbA = 1;
    int nbB = nb - nbA;

    prep_weights<<<80, 1024>>>(kW1, vW1, kW2, vW2);
    edge_feat_kernel<<<(E + 255) / 256, 256>>>(pos, bond_row, bond_col, E);
    q_mlp_kernel<<<(E + 127) / 128, NTQ, SMEM_Q>>>(h_bond, qW1, qb1, qg, qb, qW2, qb2, E);
    triplet_mma_kernel<<<nbA, NTT, SMEM_T>>>(
        h_bond, pos, kb1, kg, kb, kb2, vb1, vg, vb, vb2,
        idx_i, idx_j, idx_k, idx_kj, idx_ji, 0, T);
    if (nbB > 0)
        triplet_mma_kernel<<<nbB, NTT, SMEM_T>>>(
            h_bond, pos, kb1, kg, kb, kb2, vb1, vg, vb, vb2,
            idx_i, idx_j, idx_k, idx_kj, idx_ji, nbA, T);
    attn_out_kernel<<<(E * 32 + 255) / 256, 256>>>(idx_ji, T, E, (float*)d_out);
}